// round 1
// baseline (speedup 1.0000x reference)
#include <cuda_runtime.h>
#include <math.h>

#define N_REFP 50000
#define N_QP   25000
#define NEDGE  400000
#define C0     128
#define C1     256
#define BN_EPS 1e-5f
#define STAT_BLOCKS 256

// ---------------- scratch (static device globals; no allocation) ----------------
__device__ float d_w[NEDGE];
__device__ float d_wsum[N_QP];
__device__ int   d_deg[N_QP];
__device__ int   d_cursor[N_QP];
__device__ int   d_rowstart[N_QP + 1];
__device__ int   d_esorted[NEDGE];
__device__ float d_Y1[(size_t)N_REFP * C0];   // ref_feat @ Wf0
__device__ float d_QF[(size_t)N_QP * C0];     // aggregated (already BN'd)
__device__ float d_S [(size_t)N_QP * C0];     // query_feat @ Ws0
__device__ float d_X0[(size_t)N_QP * C0];
__device__ float d_Y2[(size_t)N_QP * C1];
__device__ float d_X1[(size_t)N_QP * C1];
__device__ float d_Y3[(size_t)N_QP * C1];
__device__ float d_partial[STAT_BLOCKS * 512]; // per-block column sums / sumsq
__device__ float d_bna[256];
__device__ float d_bnc[256];

// ---------------- init ----------------
__global__ void k_init() {
    int i = blockIdx.x * blockDim.x + threadIdx.x;
    if (i < N_QP) { d_wsum[i] = 0.f; d_deg[i] = 0; d_cursor[i] = 0; }
}

// ---------------- edge weights + degree histogram ----------------
__global__ void k_edge(const float4* __restrict__ ref_bxyz,
                       const float4* __restrict__ query_bxyz,
                       const int* __restrict__ e_ref,
                       const int* __restrict__ e_query) {
    int e = blockIdx.x * blockDim.x + threadIdx.x;
    if (e >= NEDGE) return;
    int r = e_ref[e], q = e_query[e];
    float4 rb = ref_bxyz[r];
    float4 qb = query_bxyz[q];
    float dx = rb.y - qb.y, dy = rb.z - qb.z, dz = rb.w - qb.w;
    float dist = sqrtf(dx * dx + dy * dy + dz * dz);
    float w = 1.0f / (dist + 1e-8f);
    d_w[e] = w;
    atomicAdd(&d_wsum[q], w);
    atomicAdd(&d_deg[q], 1);
}

// ---------------- exclusive scan of degrees (single block) ----------------
__global__ void k_scan() {
    __shared__ int sd[1024];
    __shared__ int carry;
    int tid = threadIdx.x;
    if (tid == 0) carry = 0;
    __syncthreads();
    for (int base = 0; base < N_QP; base += 1024) {
        int v = (base + tid < N_QP) ? d_deg[base + tid] : 0;
        sd[tid] = v;
        __syncthreads();
        #pragma unroll
        for (int off = 1; off < 1024; off <<= 1) {
            int t = (tid >= off) ? sd[tid - off] : 0;
            __syncthreads();
            sd[tid] += t;
            __syncthreads();
        }
        if (base + tid < N_QP) d_rowstart[base + tid] = carry + sd[tid] - v;
        __syncthreads();
        if (tid == 0) carry += sd[1023];
        __syncthreads();
    }
    if (tid == 0) d_rowstart[N_QP] = carry;
}

// ---------------- bucket-fill sorted edge list ----------------
__global__ void k_fill(const int* __restrict__ e_query) {
    int e = blockIdx.x * blockDim.x + threadIdx.x;
    if (e >= NEDGE) return;
    int q = e_query[e];
    int pos = atomicAdd(&d_cursor[q], 1);
    d_esorted[d_rowstart[q] + pos] = e;
}

// ---------------- fp32 SGEMM: C[M,N] = A[M,K] @ B[K,N]; K%8==0, N%128==0 ----
#define BM 128
#define BNT 128
#define BK 8
__global__ __launch_bounds__(256, 2)
void k_sgemm(const float* __restrict__ A, const float* __restrict__ B,
             float* __restrict__ C, int M, int N, int K) {
    __shared__ float As[2][BK][BM];
    __shared__ float Bs[2][BK][BNT];
    int tid = threadIdx.x;
    int tx = tid & 15, ty = tid >> 4;
    int bm = blockIdx.x * BM;
    int bn = blockIdx.y * BNT;

    int arow = tid >> 1;
    int acol = (tid & 1) * 4;
    int brow = tid >> 5;
    int bcol = (tid & 31) * 4;
    bool avalid = (bm + arow) < M;
    const float* Aptr = A + (size_t)(bm + arow) * K + acol;
    const float* Bptr = B + (size_t)brow * N + bn + bcol;

    float acc[8][8];
    #pragma unroll
    for (int i = 0; i < 8; i++)
        #pragma unroll
        for (int j = 0; j < 8; j++) acc[i][j] = 0.f;

    float4 av = avalid ? *(const float4*)Aptr : make_float4(0, 0, 0, 0);
    float4 bv = *(const float4*)Bptr;
    As[0][acol + 0][arow] = av.x; As[0][acol + 1][arow] = av.y;
    As[0][acol + 2][arow] = av.z; As[0][acol + 3][arow] = av.w;
    *(float4*)&Bs[0][brow][bcol] = bv;
    __syncthreads();

    int nt = K / BK;
    int buf = 0;
    for (int t = 0; t < nt; t++) {
        if (t + 1 < nt) {
            av = avalid ? *(const float4*)(Aptr + (t + 1) * BK) : make_float4(0, 0, 0, 0);
            bv = *(const float4*)(Bptr + (size_t)(t + 1) * BK * N);
        }
        #pragma unroll
        for (int kk = 0; kk < BK; kk++) {
            float ar[8], br[8];
            float4 a0 = *(const float4*)&As[buf][kk][ty * 8];
            float4 a1 = *(const float4*)&As[buf][kk][ty * 8 + 4];
            float4 b0 = *(const float4*)&Bs[buf][kk][tx * 8];
            float4 b1 = *(const float4*)&Bs[buf][kk][tx * 8 + 4];
            ar[0] = a0.x; ar[1] = a0.y; ar[2] = a0.z; ar[3] = a0.w;
            ar[4] = a1.x; ar[5] = a1.y; ar[6] = a1.z; ar[7] = a1.w;
            br[0] = b0.x; br[1] = b0.y; br[2] = b0.z; br[3] = b0.w;
            br[4] = b1.x; br[5] = b1.y; br[6] = b1.z; br[7] = b1.w;
            #pragma unroll
            for (int i = 0; i < 8; i++)
                #pragma unroll
                for (int j = 0; j < 8; j++)
                    acc[i][j] = fmaf(ar[i], br[j], acc[i][j]);
        }
        if (t + 1 < nt) {
            As[buf ^ 1][acol + 0][arow] = av.x; As[buf ^ 1][acol + 1][arow] = av.y;
            As[buf ^ 1][acol + 2][arow] = av.z; As[buf ^ 1][acol + 3][arow] = av.w;
            *(float4*)&Bs[buf ^ 1][brow][bcol] = bv;
        }
        __syncthreads();
        buf ^= 1;
    }

    #pragma unroll
    for (int i = 0; i < 8; i++) {
        int row = bm + ty * 8 + i;
        if (row < M) {
            #pragma unroll
            for (int j = 0; j < 8; j += 4) {
                float4 v = make_float4(acc[i][j], acc[i][j + 1], acc[i][j + 2], acc[i][j + 3]);
                *(float4*)&C[(size_t)row * N + bn + tx * 8 + j] = v;
            }
        }
    }
}

// ---------------- column stats (two-stage, deterministic) ----------------
// blockDim.x == C (128 or 256). Writes d_partial[b*512 + c] = sum, [b*512+256+c] = sumsq
__global__ void k_colstats(const float* __restrict__ Y, int M, int C) {
    int c = threadIdx.x;
    float s = 0.f, s2 = 0.f;
    for (int r = blockIdx.x; r < M; r += gridDim.x) {
        float v = Y[(size_t)r * C + c];
        s += v;
        s2 = fmaf(v, v, s2);
    }
    d_partial[blockIdx.x * 512 + c] = s;
    d_partial[blockIdx.x * 512 + 256 + c] = s2;
}

// 1 block, 256 threads
__global__ void k_bnfinal(int C, int M,
                          const float* __restrict__ g, const float* __restrict__ b) {
    int c = threadIdx.x;
    if (c >= C) return;
    float s = 0.f, s2 = 0.f;
    for (int bq = 0; bq < STAT_BLOCKS; bq++) {
        s += d_partial[bq * 512 + c];
        s2 += d_partial[bq * 512 + 256 + c];
    }
    float m = s / (float)M;
    float v = s2 / (float)M - m * m;
    float a = g[c] * rsqrtf(v + BN_EPS);
    d_bna[c] = a;
    d_bnc[c] = b[c] - a * m;
}

// ---------------- per-query gather (atomic-free segment sum) ----------------
// Since normalized weights sum to 1: qf = a0 * (sum w*Y1)/wsum + c0
__global__ void k_gather(const int* __restrict__ e_ref) {
    int q = blockIdx.x;
    int c = threadIdx.x;
    int s = d_rowstart[q], t = d_rowstart[q + 1];
    float acc = 0.f;
    for (int i = s; i < t; i++) {
        int e = d_esorted[i];
        int r = e_ref[e];
        acc = fmaf(d_w[e], d_Y1[(size_t)r * C0 + c], acc);
    }
    float outv = 0.f;
    if (t > s) outv = d_bna[c] * acc * (1.0f / d_wsum[q]) + d_bnc[c];
    d_QF[(size_t)q * C0 + c] = outv;
}

// ---------------- x0 = relu(qf + BN(S)) ----------------
__global__ void k_x0() {
    int i = blockIdx.x * blockDim.x + threadIdx.x;
    if (i >= N_QP * C0) return;
    int c = i & (C0 - 1);
    float v = d_QF[i] + d_bna[c] * d_S[i] + d_bnc[c];
    d_X0[i] = fmaxf(v, 0.f);
}

// ---------------- X = relu(a*Y + c), C=256 ----------------
__global__ void k_bnrelu(const float* __restrict__ Y, float* __restrict__ X, int n) {
    int i = blockIdx.x * blockDim.x + threadIdx.x;
    if (i >= n) return;
    int c = i & 255;
    X[i] = fmaxf(d_bna[c] * Y[i] + d_bnc[c], 0.f);
}

// ---------------- launcher ----------------
extern "C" void kernel_launch(void* const* d_in, const int* in_sizes, int n_in,
                              void* d_out, int out_size) {
    const float* ref_bxyz   = (const float*)d_in[0];
    const float* ref_feat   = (const float*)d_in[1];
    const float* query_bxyz = (const float*)d_in[2];
    const float* query_feat = (const float*)d_in[3];
    const int*   e_ref      = (const int*)d_in[4];
    const int*   e_query    = (const int*)d_in[5];
    const float* Wf0   = (const float*)d_in[6];
    const float* gf0   = (const float*)d_in[7];
    const float* bf0   = (const float*)d_in[8];
    const float* Ws0   = (const float*)d_in[9];
    const float* gs0   = (const float*)d_in[10];
    const float* bs0   = (const float*)d_in[11];
    const float* W1    = (const float*)d_in[12];
    // d_in[13] = b1: absorbed by BN mean subtraction (mathematical no-op)
    const float* g1    = (const float*)d_in[14];
    const float* beta1 = (const float*)d_in[15];
    const float* W2    = (const float*)d_in[16];
    // d_in[17] = b2: absorbed by BN
    const float* g2    = (const float*)d_in[18];
    const float* beta2 = (const float*)d_in[19];
    float* out = (float*)d_out;

    float *pY1, *pS, *pX0, *pY2, *pX1, *pY3;
    cudaGetSymbolAddress((void**)&pY1, d_Y1);
    cudaGetSymbolAddress((void**)&pS,  d_S);
    cudaGetSymbolAddress((void**)&pX0, d_X0);
    cudaGetSymbolAddress((void**)&pY2, d_Y2);
    cudaGetSymbolAddress((void**)&pX1, d_X1);
    cudaGetSymbolAddress((void**)&pY3, d_Y3);

    // edge preprocessing: weights, wsum, degree histogram, CSR sort
    k_init<<<(N_QP + 255) / 256, 256>>>();
    k_edge<<<(NEDGE + 255) / 256, 256>>>((const float4*)ref_bxyz, (const float4*)query_bxyz,
                                         e_ref, e_query);
    k_scan<<<1, 1024>>>();
    k_fill<<<(NEDGE + 255) / 256, 256>>>(e_query);

    // stage 0a: Y1 = ref_feat @ Wf0, BN params
    {
        dim3 g((N_REFP + BM - 1) / BM, C0 / BNT);
        k_sgemm<<<g, 256>>>(ref_feat, Wf0, pY1, N_REFP, C0, C0);
    }
    k_colstats<<<STAT_BLOCKS, C0>>>(pY1, N_REFP, C0);
    k_bnfinal<<<1, 256>>>(C0, N_REFP, gf0, bf0);

    // stage 0b: gather to query nodes (applies ref BN)
    k_gather<<<N_QP, C0>>>(e_ref);

    // stage 0c: skip branch S = query_feat @ Ws0, BN params
    {
        dim3 g((N_QP + BM - 1) / BM, C0 / BNT);
        k_sgemm<<<g, 256>>>(query_feat, Ws0, pS, N_QP, C0, C0);
    }
    k_colstats<<<STAT_BLOCKS, C0>>>(pS, N_QP, C0);
    k_bnfinal<<<1, 256>>>(C0, N_QP, gs0, bs0);

    // x0 = relu(qf + BN(S))
    k_x0<<<(N_QP * C0 + 255) / 256, 256>>>();

    // stage 1: x1 = relu(BN(x0 @ W1))   (b1 absorbed)
    {
        dim3 g((N_QP + BM - 1) / BM, C1 / BNT);
        k_sgemm<<<g, 256>>>(pX0, W1, pY2, N_QP, C1, C0);
    }
    k_colstats<<<STAT_BLOCKS, C1>>>(pY2, N_QP, C1);
    k_bnfinal<<<1, 256>>>(C1, N_QP, g1, beta1);
    k_bnrelu<<<(N_QP * C1 + 255) / 256, 256>>>(pY2, pX1, N_QP * C1);

    // stage 2: out = relu(BN(x1 @ W2))  (b2 absorbed)
    {
        dim3 g((N_QP + BM - 1) / BM, C1 / BNT);
        k_sgemm<<<g, 256>>>(pX1, W2, pY3, N_QP, C1, C1);
    }
    k_colstats<<<STAT_BLOCKS, C1>>>(pY3, N_QP, C1);
    k_bnfinal<<<1, 256>>>(C1, N_QP, g2, beta2);
    k_bnrelu<<<(N_QP * C1 + 255) / 256, 256>>>(pY3, out, N_QP * C1);
}

// round 3
// speedup vs baseline: 1.2907x; 1.2907x over previous
#include <cuda_runtime.h>
#include <cuda_bf16.h>
#include <math.h>
#include <cstdint>

#define N_REFP 50000
#define N_QP   25000
#define NEDGE  400000
#define C0     128
#define C1     256
#define BN_EPS 1e-5f
#define STAT_BLOCKS 256

// ---------------- scratch (static device globals; no allocation) ----------------
__device__ float d_w[NEDGE];
__device__ float d_wsum[N_QP];
__device__ int   d_deg[N_QP];
__device__ int   d_cursor[N_QP];
__device__ int   d_rowstart[N_QP + 1];
__device__ int   d_esorted[NEDGE];
__device__ float d_Y1[(size_t)N_REFP * C0];   // ref_feat @ Wf0
__device__ float d_QF[(size_t)N_QP * C0];     // aggregated (already BN'd)
__device__ float d_S [(size_t)N_QP * C0];     // query_feat @ Ws0
__device__ float d_X0[(size_t)N_QP * C0];
__device__ float d_Y2[(size_t)N_QP * C1];
__device__ float d_X1[(size_t)N_QP * C1];
__device__ float d_Y3[(size_t)N_QP * C1];
__device__ float d_partial[STAT_BLOCKS * 512];
__device__ float d_bna[256];
__device__ float d_bnc[256];

// ======================= helpers =======================
__device__ __forceinline__ uint32_t smem_u32(const void* p) {
    uint32_t a;
    asm("{ .reg .u64 t; cvta.to.shared.u64 t, %1; cvt.u32.u64 %0, t; }" : "=r"(a) : "l"(p));
    return a;
}
__device__ __forceinline__ void ldsm_x4(uint32_t& r0, uint32_t& r1, uint32_t& r2, uint32_t& r3,
                                        uint32_t addr) {
    asm volatile("ldmatrix.sync.aligned.m8n8.x4.shared.b16 {%0,%1,%2,%3}, [%4];"
                 : "=r"(r0), "=r"(r1), "=r"(r2), "=r"(r3) : "r"(addr));
}
__device__ __forceinline__ void ldsm_x4_t(uint32_t& r0, uint32_t& r1, uint32_t& r2, uint32_t& r3,
                                          uint32_t addr) {
    asm volatile("ldmatrix.sync.aligned.m8n8.x4.trans.shared.b16 {%0,%1,%2,%3}, [%4];"
                 : "=r"(r0), "=r"(r1), "=r"(r2), "=r"(r3) : "r"(addr));
}
__device__ __forceinline__ void mma_bf16(float* c, const uint32_t* a, const uint32_t* b) {
    asm volatile(
        "mma.sync.aligned.m16n8k16.row.col.f32.bf16.bf16.f32 "
        "{%0,%1,%2,%3}, {%4,%5,%6,%7}, {%8,%9}, {%0,%1,%2,%3};"
        : "+f"(c[0]), "+f"(c[1]), "+f"(c[2]), "+f"(c[3])
        : "r"(a[0]), "r"(a[1]), "r"(a[2]), "r"(a[3]), "r"(b[0]), "r"(b[1]));
}

// ---------------- split-bf16 tensor-core GEMM: C[M,N] = A[M,K] @ B[K,N] ----------------
// grid = (ceil(M/128), N/128), block = 256 (8 warps, 2x4 warp grid, 64x32 warp tiles)
// K multiple of 32. Error ~2^-18 (drops Al*Bl only).
#define KC 32
#define A_STRIDE 40    // bf16 elems per A smem row (32 + 8 pad: conflict-free ldmatrix)
#define B_STRIDE 136   // bf16 elems per B smem row (128 + 8 pad)
__global__ __launch_bounds__(256, 2)
void k_mma(const float* __restrict__ A, const float* __restrict__ B,
           float* __restrict__ C, int M, int N, int K) {
    __shared__ __align__(16) uint16_t sAh[128 * A_STRIDE];
    __shared__ __align__(16) uint16_t sAl[128 * A_STRIDE];
    __shared__ __align__(16) uint16_t sBh[KC * B_STRIDE];
    __shared__ __align__(16) uint16_t sBl[KC * B_STRIDE];
    int tid = threadIdx.x, wid = tid >> 5, lane = tid & 31;
    int bm = blockIdx.x * 128, bn = blockIdx.y * 128;
    int wm = (wid & 1) * 64, wn = (wid >> 1) * 32;
    int mat = lane >> 3, r = lane & 7;

    float acc[4][4][4];
    #pragma unroll
    for (int i = 0; i < 4; i++)
        #pragma unroll
        for (int j = 0; j < 4; j++)
            #pragma unroll
            for (int v = 0; v < 4; v++) acc[i][j][v] = 0.f;

    for (int kb = 0; kb < K; kb += KC) {
        __syncthreads();
        // convert A chunk: 128 rows x 32 k
        #pragma unroll
        for (int i = tid; i < 128 * KC; i += 256) {
            int row = i >> 5, c = i & 31;
            float v = 0.f;
            if (bm + row < M) v = A[(size_t)(bm + row) * K + kb + c];
            __nv_bfloat16 h = __float2bfloat16(v);
            __nv_bfloat16 lo = __float2bfloat16(v - __bfloat162float(h));
            sAh[row * A_STRIDE + c] = *(uint16_t*)&h;
            sAl[row * A_STRIDE + c] = *(uint16_t*)&lo;
        }
        // convert B chunk: 32 k x 128 n
        #pragma unroll
        for (int i = tid; i < KC * 128; i += 256) {
            int k = i >> 7, n = i & 127;
            float v = B[(size_t)(kb + k) * N + bn + n];
            __nv_bfloat16 h = __float2bfloat16(v);
            __nv_bfloat16 lo = __float2bfloat16(v - __bfloat162float(h));
            sBh[k * B_STRIDE + n] = *(uint16_t*)&h;
            sBl[k * B_STRIDE + n] = *(uint16_t*)&lo;
        }
        __syncthreads();

        #pragma unroll
        for (int ks = 0; ks < KC / 16; ks++) {
            #pragma unroll
            for (int t = 0; t < 3; t++) {
                const uint16_t* pa = (t < 2) ? sAh : sAl;
                const uint16_t* pb = (t == 1) ? sBl : sBh;
                uint32_t a[4][4], b[4][2];
                #pragma unroll
                for (int mt = 0; mt < 4; mt++) {
                    int mrow = wm + mt * 16 + (mat & 1) * 8 + r;
                    int kcol = ks * 16 + (mat >> 1) * 8;
                    ldsm_x4(a[mt][0], a[mt][1], a[mt][2], a[mt][3],
                            smem_u32(&pa[mrow * A_STRIDE + kcol]));
                }
                #pragma unroll
                for (int nt = 0; nt < 2; nt++) {
                    int krow = ks * 16 + (mat & 1) * 8 + r;
                    int ncol = wn + nt * 16 + (mat >> 1) * 8;
                    ldsm_x4_t(b[nt * 2][0], b[nt * 2][1], b[nt * 2 + 1][0], b[nt * 2 + 1][1],
                              smem_u32(&pb[krow * B_STRIDE + ncol]));
                }
                #pragma unroll
                for (int mt = 0; mt < 4; mt++)
                    #pragma unroll
                    for (int nt = 0; nt < 4; nt++)
                        mma_bf16(acc[mt][nt], a[mt], b[nt]);
            }
        }
    }

    // epilogue: direct fp32 stores
    int g = lane >> 2, tg = lane & 3;
    #pragma unroll
    for (int mt = 0; mt < 4; mt++) {
        #pragma unroll
        for (int nt = 0; nt < 4; nt++) {
            int row0 = bm + wm + mt * 16 + g;
            int col = bn + wn + nt * 8 + tg * 2;
            if (row0 < M) {
                C[(size_t)row0 * N + col] = acc[mt][nt][0];
                C[(size_t)row0 * N + col + 1] = acc[mt][nt][1];
            }
            int row1 = row0 + 8;
            if (row1 < M) {
                C[(size_t)row1 * N + col] = acc[mt][nt][2];
                C[(size_t)row1 * N + col + 1] = acc[mt][nt][3];
            }
        }
    }
}

// ---------------- init ----------------
__global__ void k_init() {
    int i = blockIdx.x * blockDim.x + threadIdx.x;
    if (i < N_QP) { d_wsum[i] = 0.f; d_deg[i] = 0; d_cursor[i] = 0; }
}

// ---------------- edge weights + degree histogram ----------------
__global__ void k_edge(const float4* __restrict__ ref_bxyz,
                       const float4* __restrict__ query_bxyz,
                       const int* __restrict__ e_ref,
                       const int* __restrict__ e_query) {
    int e = blockIdx.x * blockDim.x + threadIdx.x;
    if (e >= NEDGE) return;
    int r = e_ref[e], q = e_query[e];
    float4 rb = ref_bxyz[r];
    float4 qb = query_bxyz[q];
    float dx = rb.y - qb.y, dy = rb.z - qb.z, dz = rb.w - qb.w;
    float dist = sqrtf(dx * dx + dy * dy + dz * dz);
    float w = 1.0f / (dist + 1e-8f);
    d_w[e] = w;
    atomicAdd(&d_wsum[q], w);
    atomicAdd(&d_deg[q], 1);
}

// ---------------- exclusive scan of degrees (single block) ----------------
__global__ void k_scan() {
    __shared__ int sd[1024];
    __shared__ int carry;
    int tid = threadIdx.x;
    if (tid == 0) carry = 0;
    __syncthreads();
    for (int base = 0; base < N_QP; base += 1024) {
        int v = (base + tid < N_QP) ? d_deg[base + tid] : 0;
        sd[tid] = v;
        __syncthreads();
        #pragma unroll
        for (int off = 1; off < 1024; off <<= 1) {
            int t = (tid >= off) ? sd[tid - off] : 0;
            __syncthreads();
            sd[tid] += t;
            __syncthreads();
        }
        if (base + tid < N_QP) d_rowstart[base + tid] = carry + sd[tid] - v;
        __syncthreads();
        if (tid == 0) carry += sd[1023];
        __syncthreads();
    }
    if (tid == 0) d_rowstart[N_QP] = carry;
}

// ---------------- bucket-fill sorted edge list ----------------
__global__ void k_fill(const int* __restrict__ e_query) {
    int e = blockIdx.x * blockDim.x + threadIdx.x;
    if (e >= NEDGE) return;
    int q = e_query[e];
    int pos = atomicAdd(&d_cursor[q], 1);
    d_esorted[d_rowstart[q] + pos] = e;
}

// ---------------- column stats (two-stage, deterministic) ----------------
__global__ void k_colstats(const float* __restrict__ Y, int M, int C) {
    int c = threadIdx.x;
    float s = 0.f, s2 = 0.f;
    for (int r = blockIdx.x; r < M; r += gridDim.x) {
        float v = Y[(size_t)r * C + c];
        s += v;
        s2 = fmaf(v, v, s2);
    }
    d_partial[blockIdx.x * 512 + c] = s;
    d_partial[blockIdx.x * 512 + 256 + c] = s2;
}

__global__ void k_bnfinal(int C, int M,
                          const float* __restrict__ g, const float* __restrict__ b) {
    int c = threadIdx.x;
    if (c >= C) return;
    float s = 0.f, s2 = 0.f;
    for (int bq = 0; bq < STAT_BLOCKS; bq++) {
        s += d_partial[bq * 512 + c];
        s2 += d_partial[bq * 512 + 256 + c];
    }
    float m = s / (float)M;
    float v = s2 / (float)M - m * m;
    float a = g[c] * rsqrtf(v + BN_EPS);
    d_bna[c] = a;
    d_bnc[c] = b[c] - a * m;
}

// ---------------- per-query gather (atomic-free segment sum) ----------------
__global__ void k_gather(const int* __restrict__ e_ref) {
    int q = blockIdx.x;
    int c = threadIdx.x;
    int s = d_rowstart[q], t = d_rowstart[q + 1];
    float acc = 0.f;
    for (int i = s; i < t; i++) {
        int e = d_esorted[i];
        int r = e_ref[e];
        acc = fmaf(d_w[e], d_Y1[(size_t)r * C0 + c], acc);
    }
    float outv = 0.f;
    if (t > s) outv = d_bna[c] * acc * (1.0f / d_wsum[q]) + d_bnc[c];
    d_QF[(size_t)q * C0 + c] = outv;
}

// ---------------- x0 = relu(qf + BN(S)) ----------------
__global__ void k_x0() {
    int i = blockIdx.x * blockDim.x + threadIdx.x;
    if (i >= N_QP * C0) return;
    int c = i & (C0 - 1);
    float v = d_QF[i] + d_bna[c] * d_S[i] + d_bnc[c];
    d_X0[i] = fmaxf(v, 0.f);
}

// ---------------- X = relu(a*Y + c), C=256 ----------------
__global__ void k_bnrelu(const float* __restrict__ Y, float* __restrict__ X, int n) {
    int i = blockIdx.x * blockDim.x + threadIdx.x;
    if (i >= n) return;
    int c = i & 255;
    X[i] = fmaxf(d_bna[c] * Y[i] + d_bnc[c], 0.f);
}

// ---------------- launcher ----------------
extern "C" void kernel_launch(void* const* d_in, const int* in_sizes, int n_in,
                              void* d_out, int out_size) {
    const float* ref_bxyz   = (const float*)d_in[0];
    const float* ref_feat   = (const float*)d_in[1];
    const float* query_bxyz = (const float*)d_in[2];
    const float* query_feat = (const float*)d_in[3];
    const int*   e_ref      = (const int*)d_in[4];
    const int*   e_query    = (const int*)d_in[5];
    const float* Wf0   = (const float*)d_in[6];
    const float* gf0   = (const float*)d_in[7];
    const float* bf0   = (const float*)d_in[8];
    const float* Ws0   = (const float*)d_in[9];
    const float* gs0   = (const float*)d_in[10];
    const float* bs0   = (const float*)d_in[11];
    const float* W1    = (const float*)d_in[12];
    const float* g1    = (const float*)d_in[14];
    const float* beta1 = (const float*)d_in[15];
    const float* W2    = (const float*)d_in[16];
    const float* g2    = (const float*)d_in[18];
    const float* beta2 = (const float*)d_in[19];
    float* out = (float*)d_out;

    float *pY1, *pS, *pX0, *pY2, *pX1, *pY3;
    cudaGetSymbolAddress((void**)&pY1, d_Y1);
    cudaGetSymbolAddress((void**)&pS,  d_S);
    cudaGetSymbolAddress((void**)&pX0, d_X0);
    cudaGetSymbolAddress((void**)&pY2, d_Y2);
    cudaGetSymbolAddress((void**)&pX1, d_X1);
    cudaGetSymbolAddress((void**)&pY3, d_Y3);

    // edge preprocessing
    k_init<<<(N_QP + 255) / 256, 256>>>();
    k_edge<<<(NEDGE + 255) / 256, 256>>>((const float4*)ref_bxyz, (const float4*)query_bxyz,
                                         e_ref, e_query);
    k_scan<<<1, 1024>>>();
    k_fill<<<(NEDGE + 255) / 256, 256>>>(e_query);

    // stage 0a: Y1 = ref_feat @ Wf0
    {
        dim3 g((N_REFP + 127) / 128, C0 / 128);
        k_mma<<<g, 256>>>(ref_feat, Wf0, pY1, N_REFP, C0, C0);
    }
    k_colstats<<<STAT_BLOCKS, C0>>>(pY1, N_REFP, C0);
    k_bnfinal<<<1, 256>>>(C0, N_REFP, gf0, bf0);

    // stage 0b: gather to query nodes (applies ref BN)
    k_gather<<<N_QP, C0>>>(e_ref);

    // stage 0c: skip branch S = query_feat @ Ws0
    {
        dim3 g((N_QP + 127) / 128, C0 / 128);
        k_mma<<<g, 256>>>(query_feat, Ws0, pS, N_QP, C0, C0);
    }
    k_colstats<<<STAT_BLOCKS, C0>>>(pS, N_QP, C0);
    k_bnfinal<<<1, 256>>>(C0, N_QP, gs0, bs0);

    k_x0<<<(N_QP * C0 + 255) / 256, 256>>>();

    // stage 1: x1 = relu(BN(x0 @ W1))  (b1 absorbed by BN)
    {
        dim3 g((N_QP + 127) / 128, C1 / 128);
        k_mma<<<g, 256>>>(pX0, W1, pY2, N_QP, C1, C0);
    }
    k_colstats<<<STAT_BLOCKS, C1>>>(pY2, N_QP, C1);
    k_bnfinal<<<1, 256>>>(C1, N_QP, g1, beta1);
    k_bnrelu<<<(N_QP * C1 + 255) / 256, 256>>>(pY2, pX1, N_QP * C1);

    // stage 2: out = relu(BN(x1 @ W2))  (b2 absorbed by BN)
    {
        dim3 g((N_QP + 127) / 128, C1 / 128);
        k_mma<<<g, 256>>>(pX1, W2, pY3, N_QP, C1, C1);
    }
    k_colstats<<<STAT_BLOCKS, C1>>>(pY3, N_QP, C1);
    k_bnfinal<<<1, 256>>>(C1, N_QP, g2, beta2);
    k_bnrelu<<<(N_QP * C1 + 255) / 256, 256>>>(pY3, out, N_QP * C1);
}

// round 5
// speedup vs baseline: 1.3211x; 1.0236x over previous
#include <cuda_runtime.h>
#include <cuda_bf16.h>
#include <math.h>
#include <cstdint>

#define N_REFP 50000
#define N_QP   25000
#define NEDGE  400000
#define C0     128
#define C1     256
#define BN_EPS 1e-5f
#define STAT_BLOCKS 256

// ---------------- scratch (static device globals; no allocation) ----------------
__device__ float d_w[NEDGE];
__device__ float d_wsum[N_QP];
__device__ int   d_deg[N_QP];
__device__ int   d_cursor[N_QP];
__device__ int   d_rowstart[N_QP + 1];
__device__ int   d_esorted[NEDGE];
__device__ float d_Y1[(size_t)N_REFP * C0];
__device__ float d_QF[(size_t)N_QP * C0];
__device__ float d_S [(size_t)N_QP * C0];
__device__ float d_Y2[(size_t)N_QP * C1];
__device__ float d_Y3[(size_t)N_QP * C1];
__device__ float d_partial[STAT_BLOCKS * 512];
__device__ float d_bna[256];
__device__ float d_bnc[256];
// split-bf16 operands
__device__ __nv_bfloat16 d_refH[(size_t)N_REFP * C0], d_refL[(size_t)N_REFP * C0];
__device__ __nv_bfloat16 d_qH[(size_t)N_QP * C0],     d_qL[(size_t)N_QP * C0];
__device__ __nv_bfloat16 d_X0H[(size_t)N_QP * C0],    d_X0L[(size_t)N_QP * C0];
__device__ __nv_bfloat16 d_X1H[(size_t)N_QP * C1],    d_X1L[(size_t)N_QP * C1];
__device__ __nv_bfloat16 d_Wf0H[C0 * C0], d_Wf0L[C0 * C0];
__device__ __nv_bfloat16 d_Ws0H[C0 * C0], d_Ws0L[C0 * C0];
__device__ __nv_bfloat16 d_W1H[C0 * C1],  d_W1L[C0 * C1];
__device__ __nv_bfloat16 d_W2H[C1 * C1],  d_W2L[C1 * C1];

// ======================= helpers =======================
__device__ __forceinline__ uint32_t smem_u32(const void* p) {
    uint32_t a;
    asm("{ .reg .u64 t; cvta.to.shared.u64 t, %1; cvt.u32.u64 %0, t; }" : "=r"(a) : "l"(p));
    return a;
}
__device__ __forceinline__ void ldsm_x4(uint32_t& r0, uint32_t& r1, uint32_t& r2, uint32_t& r3,
                                        uint32_t addr) {
    asm volatile("ldmatrix.sync.aligned.m8n8.x4.shared.b16 {%0,%1,%2,%3}, [%4];"
                 : "=r"(r0), "=r"(r1), "=r"(r2), "=r"(r3) : "r"(addr));
}
__device__ __forceinline__ void ldsm_x4_t(uint32_t& r0, uint32_t& r1, uint32_t& r2, uint32_t& r3,
                                          uint32_t addr) {
    asm volatile("ldmatrix.sync.aligned.m8n8.x4.trans.shared.b16 {%0,%1,%2,%3}, [%4];"
                 : "=r"(r0), "=r"(r1), "=r"(r2), "=r"(r3) : "r"(addr));
}
__device__ __forceinline__ void mma_bf16(float* c, const uint32_t* a, const uint32_t* b) {
    asm volatile(
        "mma.sync.aligned.m16n8k16.row.col.f32.bf16.bf16.f32 "
        "{%0,%1,%2,%3}, {%4,%5,%6,%7}, {%8,%9}, {%0,%1,%2,%3};"
        : "+f"(c[0]), "+f"(c[1]), "+f"(c[2]), "+f"(c[3])
        : "r"(a[0]), "r"(a[1]), "r"(a[2]), "r"(a[3]), "r"(b[0]), "r"(b[1]));
}
__device__ __forceinline__ void cpa16(uint32_t dst, const void* src, int valid) {
    asm volatile("cp.async.cg.shared.global [%0], [%1], 16, %2;"
                 :: "r"(dst), "l"(src), "r"(valid ? 16 : 0) : "memory");
}
__device__ __forceinline__ void split2(float v, uint16_t& h, uint16_t& l) {
    __nv_bfloat16 bh = __float2bfloat16(v);
    __nv_bfloat16 bl = __float2bfloat16(v - __bfloat162float(bh));
    h = *(uint16_t*)&bh; l = *(uint16_t*)&bl;
}

// ---------------- split kernel: fp32 -> (hi, lo) bf16 ----------------
__global__ void k_split(const float* __restrict__ X, __nv_bfloat16* __restrict__ H,
                        __nv_bfloat16* __restrict__ L, int n) {
    int i = (blockIdx.x * blockDim.x + threadIdx.x) * 4;
    if (i >= n) return;
    float4 v = *(const float4*)(X + i);
    uint16_t h[4], l[4];
    split2(v.x, h[0], l[0]); split2(v.y, h[1], l[1]);
    split2(v.z, h[2], l[2]); split2(v.w, h[3], l[3]);
    *(uint2*)((uint16_t*)H + i) = make_uint2(h[0] | ((uint32_t)h[1] << 16), h[2] | ((uint32_t)h[3] << 16));
    *(uint2*)((uint16_t*)L + i) = make_uint2(l[0] | ((uint32_t)l[1] << 16), l[2] | ((uint32_t)l[3] << 16));
}

// ---------------- pipelined split-bf16 GEMM ----------------
// C[M,N] = (Ah+Al)[M,K] @ (Bh+Bl)[K,N] (drops Al*Bl).
// grid=(ceil(M/128), N/128), block=256. K in {128,256}. Conceptual K' = 3K chunks of 32.
#define KC 32
#define A_STRIDE 40
#define B_STRIDE 136
__global__ __launch_bounds__(256, 2)
void k_mma(const __nv_bfloat16* __restrict__ Ah, const __nv_bfloat16* __restrict__ Al,
           const __nv_bfloat16* __restrict__ Bh, const __nv_bfloat16* __restrict__ Bl,
           float* __restrict__ C, int M, int N, int K) {
    __shared__ __align__(16) uint16_t sA[2][128 * A_STRIDE];
    __shared__ __align__(16) uint16_t sB[2][KC * B_STRIDE];
    int tid = threadIdx.x, wid = tid >> 5, lane = tid & 31;
    int bm = blockIdx.x * 128, bn = blockIdx.y * 128;
    int wm = (wid & 1) * 64, wn = (wid >> 1) * 32;
    int mat = lane >> 3, r = lane & 7;
    int kpt = K >> 5;            // chunks per term
    int nch = 3 * kpt;

    float acc[4][4][4];
    #pragma unroll
    for (int i = 0; i < 4; i++)
        #pragma unroll
        for (int j = 0; j < 4; j++)
            #pragma unroll
            for (int v = 0; v < 4; v++) acc[i][j][v] = 0.f;

    uint32_t aBase[2] = { smem_u32(sA[0]), smem_u32(sA[1]) };
    uint32_t bBase[2] = { smem_u32(sB[0]), smem_u32(sB[1]) };

    auto issue = [&](int c, int buf) {
        int term = c / kpt;
        int koff = (c - term * kpt) << 5;
        const __nv_bfloat16* Ap = (term < 2) ? Ah : Al;
        const __nv_bfloat16* Bp = (term == 1) ? Bl : Bh;
        #pragma unroll
        for (int i = 0; i < 2; i++) {
            int seg = i * 256 + tid;
            int row = seg >> 2, cs = (seg & 3) << 3;
            cpa16(aBase[buf] + (row * A_STRIDE + cs) * 2,
                  Ap + (size_t)(bm + row) * K + koff + cs, (bm + row) < M);
        }
        #pragma unroll
        for (int i = 0; i < 2; i++) {
            int seg = i * 256 + tid;
            int row = seg >> 4, cs = (seg & 15) << 3;
            cpa16(bBase[buf] + (row * B_STRIDE + cs) * 2,
                  Bp + (size_t)(koff + row) * N + bn + cs, 1);
        }
        asm volatile("cp.async.commit_group;" ::: "memory");
    };

    issue(0, 0);
    for (int c = 0; c < nch; c++) {
        int buf = c & 1;
        if (c + 1 < nch) {
            issue(c + 1, buf ^ 1);
            asm volatile("cp.async.wait_group 1;" ::: "memory");
        } else {
            asm volatile("cp.async.wait_group 0;" ::: "memory");
        }
        __syncthreads();
        #pragma unroll
        for (int ks = 0; ks < KC / 16; ks++) {
            uint32_t a[4][4], b[4][2];
            #pragma unroll
            for (int mt = 0; mt < 4; mt++) {
                int mrow = wm + mt * 16 + (mat & 1) * 8 + r;
                int kcol = ks * 16 + (mat >> 1) * 8;
                ldsm_x4(a[mt][0], a[mt][1], a[mt][2], a[mt][3],
                        aBase[buf] + (mrow * A_STRIDE + kcol) * 2);
            }
            #pragma unroll
            for (int nt = 0; nt < 2; nt++) {
                int krow = ks * 16 + (mat & 1) * 8 + r;
                int ncol = wn + nt * 16 + (mat >> 1) * 8;
                ldsm_x4_t(b[nt * 2][0], b[nt * 2][1], b[nt * 2 + 1][0], b[nt * 2 + 1][1],
                          bBase[buf] + (krow * B_STRIDE + ncol) * 2);
            }
            #pragma unroll
            for (int mt = 0; mt < 4; mt++)
                #pragma unroll
                for (int nt = 0; nt < 4; nt++)
                    mma_bf16(acc[mt][nt], a[mt], b[nt]);
        }
        __syncthreads();
    }

    int g = lane >> 2, tg = lane & 3;
    #pragma unroll
    for (int mt = 0; mt < 4; mt++) {
        #pragma unroll
        for (int nt = 0; nt < 4; nt++) {
            int row0 = bm + wm + mt * 16 + g;
            int col = bn + wn + nt * 8 + tg * 2;
            if (row0 < M) {
                C[(size_t)row0 * N + col] = acc[mt][nt][0];
                C[(size_t)row0 * N + col + 1] = acc[mt][nt][1];
            }
            int row1 = row0 + 8;
            if (row1 < M) {
                C[(size_t)row1 * N + col] = acc[mt][nt][2];
                C[(size_t)row1 * N + col + 1] = acc[mt][nt][3];
            }
        }
    }
}

// ---------------- init ----------------
__global__ void k_init() {
    int i = blockIdx.x * blockDim.x + threadIdx.x;
    if (i < N_QP) { d_wsum[i] = 0.f; d_deg[i] = 0; d_cursor[i] = 0; }
}

// ---------------- edge weights + degree histogram ----------------
__global__ void k_edge(const float4* __restrict__ ref_bxyz,
                       const float4* __restrict__ query_bxyz,
                       const int* __restrict__ e_ref,
                       const int* __restrict__ e_query) {
    int e = blockIdx.x * blockDim.x + threadIdx.x;
    if (e >= NEDGE) return;
    int r = e_ref[e], q = e_query[e];
    float4 rb = ref_bxyz[r];
    float4 qb = query_bxyz[q];
    float dx = rb.y - qb.y, dy = rb.z - qb.z, dz = rb.w - qb.w;
    float dist = sqrtf(dx * dx + dy * dy + dz * dz);
    float w = 1.0f / (dist + 1e-8f);
    d_w[e] = w;
    atomicAdd(&d_wsum[q], w);
    atomicAdd(&d_deg[q], 1);
}

// ---------------- single-pass scan: 1 block, 1024 threads, 25 elems/thread ----------------
__global__ void k_scan() {
    __shared__ int wsum[32];
    const int CH = 25;  // 1024*25 >= 25000
    int tid = threadIdx.x, lane = tid & 31, wid = tid >> 5;
    int base = tid * CH;
    int s = 0;
    #pragma unroll
    for (int i = 0; i < CH; i++) {
        int idx = base + i;
        if (idx < N_QP) s += d_deg[idx];
    }
    int v = s;
    #pragma unroll
    for (int off = 1; off < 32; off <<= 1) {
        int t = __shfl_up_sync(0xffffffff, v, off);
        if (lane >= off) v += t;
    }
    if (lane == 31) wsum[wid] = v;
    __syncthreads();
    if (wid == 0) {
        int w = wsum[lane];
        #pragma unroll
        for (int off = 1; off < 32; off <<= 1) {
            int t = __shfl_up_sync(0xffffffff, w, off);
            if (lane >= off) w += t;
        }
        wsum[lane] = w;
    }
    __syncthreads();
    int warp_excl = (wid == 0) ? 0 : wsum[wid - 1];
    int run = warp_excl + v - s;  // exclusive prefix at this thread's chunk start
    #pragma unroll
    for (int i = 0; i < CH; i++) {
        int idx = base + i;
        if (idx < N_QP) { d_rowstart[idx] = run; run += d_deg[idx]; }
    }
    if (base < N_QP && base + CH >= N_QP) d_rowstart[N_QP] = run;
}

// ---------------- bucket-fill sorted edge list ----------------
__global__ void k_fill(const int* __restrict__ e_query) {
    int e = blockIdx.x * blockDim.x + threadIdx.x;
    if (e >= NEDGE) return;
    int q = e_query[e];
    int pos = atomicAdd(&d_cursor[q], 1);
    d_esorted[d_rowstart[q] + pos] = e;
}

// ---------------- column stats (two-stage, deterministic) ----------------
__global__ void k_colstats(const float* __restrict__ Y, int M, int C) {
    int c = threadIdx.x;
    float s = 0.f, s2 = 0.f;
    for (int r = blockIdx.x; r < M; r += gridDim.x) {
        float v = Y[(size_t)r * C + c];
        s += v;
        s2 = fmaf(v, v, s2);
    }
    d_partial[blockIdx.x * 512 + c] = s;
    d_partial[blockIdx.x * 512 + 256 + c] = s2;
}

__global__ void k_bnfinal(int C, int M,
                          const float* __restrict__ g, const float* __restrict__ b) {
    int c = threadIdx.x;
    if (c >= C) return;
    float s = 0.f, s2 = 0.f;
    for (int bq = 0; bq < STAT_BLOCKS; bq++) {
        s += d_partial[bq * 512 + c];
        s2 += d_partial[bq * 512 + 256 + c];
    }
    float m = s / (float)M;
    float v = s2 / (float)M - m * m;
    float a = g[c] * rsqrtf(v + BN_EPS);
    d_bna[c] = a;
    d_bnc[c] = b[c] - a * m;
}

// ---------------- per-query gather (atomic-free segment sum) ----------------
__global__ void k_gather(const int* __restrict__ e_ref) {
    int q = blockIdx.x;
    int c = threadIdx.x;
    int s = d_rowstart[q], t = d_rowstart[q + 1];
    float acc = 0.f;
    for (int i = s; i < t; i++) {
        int e = d_esorted[i];
        int r = e_ref[e];
        acc = fmaf(d_w[e], d_Y1[(size_t)r * C0 + c], acc);
    }
    float outv = 0.f;
    if (t > s) outv = d_bna[c] * acc * (1.0f / d_wsum[q]) + d_bnc[c];
    d_QF[(size_t)q * C0 + c] = outv;
}

// ---------------- x0 = relu(qf + BN(S)), emit split bf16 ----------------
__global__ void k_x0() {
    int i = blockIdx.x * blockDim.x + threadIdx.x;
    if (i >= N_QP * C0) return;
    int c = i & (C0 - 1);
    float v = fmaxf(d_QF[i] + d_bna[c] * d_S[i] + d_bnc[c], 0.f);
    uint16_t h, l;
    split2(v, h, l);
    ((uint16_t*)d_X0H)[i] = h;
    ((uint16_t*)d_X0L)[i] = l;
}

// ---------------- x1 = relu(a*Y + c), emit split bf16 (C=256) ----------------
__global__ void k_bnrelu_split(const float* __restrict__ Y, int n) {
    int i = blockIdx.x * blockDim.x + threadIdx.x;
    if (i >= n) return;
    int c = i & 255;
    float v = fmaxf(d_bna[c] * Y[i] + d_bnc[c], 0.f);
    uint16_t h, l;
    split2(v, h, l);
    ((uint16_t*)d_X1H)[i] = h;
    ((uint16_t*)d_X1L)[i] = l;
}

// ---------------- out = relu(a*Y + c) fp32 (C=256) ----------------
__global__ void k_bnrelu_out(const float* __restrict__ Y, float* __restrict__ X, int n) {
    int i = blockIdx.x * blockDim.x + threadIdx.x;
    if (i >= n) return;
    int c = i & 255;
    X[i] = fmaxf(d_bna[c] * Y[i] + d_bnc[c], 0.f);
}

// ---------------- launcher ----------------
extern "C" void kernel_launch(void* const* d_in, const int* in_sizes, int n_in,
                              void* d_out, int out_size) {
    const float* ref_bxyz   = (const float*)d_in[0];
    const float* ref_feat   = (const float*)d_in[1];
    const float* query_bxyz = (const float*)d_in[2];
    const float* query_feat = (const float*)d_in[3];
    const int*   e_ref      = (const int*)d_in[4];
    const int*   e_query    = (const int*)d_in[5];
    const float* Wf0   = (const float*)d_in[6];
    const float* gf0   = (const float*)d_in[7];
    const float* bf0   = (const float*)d_in[8];
    const float* Ws0   = (const float*)d_in[9];
    const float* gs0   = (const float*)d_in[10];
    const float* bs0   = (const float*)d_in[11];
    const float* W1    = (const float*)d_in[12];
    const float* g1    = (const float*)d_in[14];
    const float* beta1 = (const float*)d_in[15];
    const float* W2    = (const float*)d_in[16];
    const float* g2    = (const float*)d_in[18];
    const float* beta2 = (const float*)d_in[19];
    float* out = (float*)d_out;

    float *pY1, *pS, *pY2, *pY3;
    cudaGetSymbolAddress((void**)&pY1, d_Y1);
    cudaGetSymbolAddress((void**)&pS,  d_S);
    cudaGetSymbolAddress((void**)&pY2, d_Y2);
    cudaGetSymbolAddress((void**)&pY3, d_Y3);
    __nv_bfloat16 *pRefH, *pRefL, *pQH, *pQL, *pX0H, *pX0L, *pX1H, *pX1L;
    __nv_bfloat16 *pWf0H, *pWf0L, *pWs0H, *pWs0L, *pW1H, *pW1L, *pW2H, *pW2L;
    cudaGetSymbolAddress((void**)&pRefH, d_refH); cudaGetSymbolAddress((void**)&pRefL, d_refL);
    cudaGetSymbolAddress((void**)&pQH, d_qH);     cudaGetSymbolAddress((void**)&pQL, d_qL);
    cudaGetSymbolAddress((void**)&pX0H, d_X0H);   cudaGetSymbolAddress((void**)&pX0L, d_X0L);
    cudaGetSymbolAddress((void**)&pX1H, d_X1H);   cudaGetSymbolAddress((void**)&pX1L, d_X1L);
    cudaGetSymbolAddress((void**)&pWf0H, d_Wf0H); cudaGetSymbolAddress((void**)&pWf0L, d_Wf0L);
    cudaGetSymbolAddress((void**)&pWs0H, d_Ws0H); cudaGetSymbolAddress((void**)&pWs0L, d_Ws0L);
    cudaGetSymbolAddress((void**)&pW1H, d_W1H);   cudaGetSymbolAddress((void**)&pW1L, d_W1L);
    cudaGetSymbolAddress((void**)&pW2H, d_W2H);   cudaGetSymbolAddress((void**)&pW2L, d_W2L);

    // 0-3: weight splits
    k_split<<<(C0 * C0 / 4 + 255) / 256, 256>>>(Wf0, pWf0H, pWf0L, C0 * C0);
    k_split<<<(C0 * C0 / 4 + 255) / 256, 256>>>(Ws0, pWs0H, pWs0L, C0 * C0);
    k_split<<<(C0 * C1 / 4 + 255) / 256, 256>>>(W1, pW1H, pW1L, C0 * C1);
    k_split<<<(C1 * C1 / 4 + 255) / 256, 256>>>(W2, pW2H, pW2L, C1 * C1);
    // 4: ref_feat split
    k_split<<<(N_REFP * C0 / 4 + 255) / 256, 256>>>(ref_feat, pRefH, pRefL, N_REFP * C0);
    // 5: GEMM Y1 = ref_feat @ Wf0  (profiled launch)
    {
        dim3 g((N_REFP + 127) / 128, C0 / 128);
        k_mma<<<g, 256>>>(pRefH, pRefL, pWf0H, pWf0L, pY1, N_REFP, C0, C0);
    }
    // edge preprocessing
    k_split<<<(N_QP * C0 / 4 + 255) / 256, 256>>>(query_feat, pQH, pQL, N_QP * C0);
    k_init<<<(N_QP + 255) / 256, 256>>>();
    k_edge<<<(NEDGE + 255) / 256, 256>>>((const float4*)ref_bxyz, (const float4*)query_bxyz,
                                         e_ref, e_query);
    k_scan<<<1, 1024>>>();
    k_fill<<<(NEDGE + 255) / 256, 256>>>(e_query);

    k_colstats<<<STAT_BLOCKS, C0>>>(pY1, N_REFP, C0);
    k_bnfinal<<<1, 256>>>(C0, N_REFP, gf0, bf0);
    k_gather<<<N_QP, C0>>>(e_ref);

    // skip branch
    {
        dim3 g((N_QP + 127) / 128, C0 / 128);
        k_mma<<<g, 256>>>(pQH, pQL, pWs0H, pWs0L, pS, N_QP, C0, C0);
    }
    k_colstats<<<STAT_BLOCKS, C0>>>(pS, N_QP, C0);
    k_bnfinal<<<1, 256>>>(C0, N_QP, gs0, bs0);
    k_x0<<<(N_QP * C0 + 255) / 256, 256>>>();

    // stage 1: x1 = relu(BN(x0 @ W1))  (b1 absorbed by BN)
    {
        dim3 g((N_QP + 127) / 128, C1 / 128);
        k_mma<<<g, 256>>>(pX0H, pX0L, pW1H, pW1L, pY2, N_QP, C1, C0);
    }
    k_colstats<<<STAT_BLOCKS, C1>>>(pY2, N_QP, C1);
    k_bnfinal<<<1, 256>>>(C1, N_QP, g1, beta1);
    k_bnrelu_split<<<(N_QP * C1 + 255) / 256, 256>>>(pY2, N_QP * C1);

    // stage 2: out = relu(BN(x1 @ W2))  (b2 absorbed by BN)
    {
        dim3 g((N_QP + 127) / 128, C1 / 128);
        k_mma<<<g, 256>>>(pX1H, pX1L, pW2H, pW2L, pY3, N_QP, C1, C1);
    }
    k_colstats<<<STAT_BLOCKS, C1>>>(pY3, N_QP, C1);
    k_bnfinal<<<1, 256>>>(C1, N_QP, g2, beta2);
    k_bnrelu_out<<<(N_QP * C1 + 255) / 256, 256>>>(pY3, out, N_QP * C1);
}

// round 7
// speedup vs baseline: 2.0199x; 1.5289x over previous
#include <cuda_runtime.h>
#include <cuda_bf16.h>
#include <math.h>
#include <cstdint>

#define N_REFP 50000
#define N_QP   25000
#define NEDGE  400000
#define C0     128
#define C1     256
#define BN_EPS 1e-5f

// ---------------- scratch ----------------
__device__ float d_w[NEDGE];
__device__ float d_wsum[N_QP];
__device__ int   d_deg[N_QP];
__device__ int   d_cursor[N_QP];
__device__ int   d_rowstart[N_QP + 1];
__device__ int   d_rsorted[NEDGE];
__device__ float d_wsorted[NEDGE];
__device__ float d_Y1[(size_t)N_REFP * C0];
__device__ float d_QF[(size_t)N_QP * C0];
__device__ float d_S [(size_t)N_QP * C0];
__device__ float d_Y2[(size_t)N_QP * C1];
__device__ float d_Y3[(size_t)N_QP * C1];
__device__ float d_partial[400 * 1024];
__device__ float d_bna[256];
__device__ float d_bnc[256];
__device__ __nv_bfloat16 d_refH[(size_t)N_REFP * C0], d_refL[(size_t)N_REFP * C0];
__device__ __nv_bfloat16 d_qH[(size_t)N_QP * C0],     d_qL[(size_t)N_QP * C0];
__device__ __nv_bfloat16 d_X0H[(size_t)N_QP * C0],    d_X0L[(size_t)N_QP * C0];
__device__ __nv_bfloat16 d_X1H[(size_t)N_QP * C1],    d_X1L[(size_t)N_QP * C1];
__device__ __nv_bfloat16 d_Wf0H[C0 * C0], d_Wf0L[C0 * C0];
__device__ __nv_bfloat16 d_Ws0H[C0 * C0], d_Ws0L[C0 * C0];
__device__ __nv_bfloat16 d_W1H[C0 * C1],  d_W1L[C0 * C1];
__device__ __nv_bfloat16 d_W2H[C1 * C1],  d_W2L[C1 * C1];

// ======================= helpers =======================
__device__ __forceinline__ uint32_t smem_u32(const void* p) {
    uint32_t a;
    asm("{ .reg .u64 t; cvta.to.shared.u64 t, %1; cvt.u32.u64 %0, t; }" : "=r"(a) : "l"(p));
    return a;
}
__device__ __forceinline__ void ldsm_x4(uint32_t& r0, uint32_t& r1, uint32_t& r2, uint32_t& r3,
                                        uint32_t addr) {
    asm volatile("ldmatrix.sync.aligned.m8n8.x4.shared.b16 {%0,%1,%2,%3}, [%4];"
                 : "=r"(r0), "=r"(r1), "=r"(r2), "=r"(r3) : "r"(addr));
}
__device__ __forceinline__ void ldsm_x4_t(uint32_t& r0, uint32_t& r1, uint32_t& r2, uint32_t& r3,
                                          uint32_t addr) {
    asm volatile("ldmatrix.sync.aligned.m8n8.x4.trans.shared.b16 {%0,%1,%2,%3}, [%4];"
                 : "=r"(r0), "=r"(r1), "=r"(r2), "=r"(r3) : "r"(addr));
}
__device__ __forceinline__ void mma_bf16(float* c, const uint32_t* a, const uint32_t* b) {
    asm volatile(
        "mma.sync.aligned.m16n8k16.row.col.f32.bf16.bf16.f32 "
        "{%0,%1,%2,%3}, {%4,%5,%6,%7}, {%8,%9}, {%0,%1,%2,%3};"
        : "+f"(c[0]), "+f"(c[1]), "+f"(c[2]), "+f"(c[3])
        : "r"(a[0]), "r"(a[1]), "r"(a[2]), "r"(a[3]), "r"(b[0]), "r"(b[1]));
}
__device__ __forceinline__ void cpa16(uint32_t dst, const void* src, int valid) {
    asm volatile("cp.async.cg.shared.global [%0], [%1], 16, %2;"
                 :: "r"(dst), "l"(src), "r"(valid ? 16 : 0) : "memory");
}
__device__ __forceinline__ void split2(float v, uint16_t& h, uint16_t& l) {
    __nv_bfloat16 bh = __float2bfloat16(v);
    __nv_bfloat16 bl = __float2bfloat16(v - __bfloat162float(bh));
    h = *(uint16_t*)&bh; l = *(uint16_t*)&bl;
}
__device__ __forceinline__ void split4_store(const float* X, uint16_t* H, uint16_t* L, int q) {
    float4 v = *(const float4*)(X + q * 4);
    uint16_t h[4], l[4];
    split2(v.x, h[0], l[0]); split2(v.y, h[1], l[1]);
    split2(v.z, h[2], l[2]); split2(v.w, h[3], l[3]);
    *(uint2*)(H + q * 4) = make_uint2(h[0] | ((uint32_t)h[1] << 16), h[2] | ((uint32_t)h[3] << 16));
    *(uint2*)(L + q * 4) = make_uint2(l[0] | ((uint32_t)l[1] << 16), l[2] | ((uint32_t)l[3] << 16));
}

// ---------------- mega split kernel: all fp32->split-bf16 conversions + init ----------------
#define QR  1600000   // ref quads
#define QQ  800000    // query quads
#define QW0 4096
#define QW1 4096
#define QW2 8192
#define QW3 16384
#define QIN 6250
#define QTOT (QR + QQ + QW0 + QW1 + QW2 + QW3 + QIN)
__global__ void k_split_all(const float* __restrict__ ref, const float* __restrict__ qf,
                            const float* __restrict__ Wf0, const float* __restrict__ Ws0,
                            const float* __restrict__ W1, const float* __restrict__ W2) {
    int i = blockIdx.x * blockDim.x + threadIdx.x;
    if (i >= QTOT) return;
    if (i < QR) { split4_store(ref, (uint16_t*)d_refH, (uint16_t*)d_refL, i); return; }
    i -= QR;
    if (i < QQ) { split4_store(qf, (uint16_t*)d_qH, (uint16_t*)d_qL, i); return; }
    i -= QQ;
    if (i < QW0) { split4_store(Wf0, (uint16_t*)d_Wf0H, (uint16_t*)d_Wf0L, i); return; }
    i -= QW0;
    if (i < QW1) { split4_store(Ws0, (uint16_t*)d_Ws0H, (uint16_t*)d_Ws0L, i); return; }
    i -= QW1;
    if (i < QW2) { split4_store(W1, (uint16_t*)d_W1H, (uint16_t*)d_W1L, i); return; }
    i -= QW2;
    if (i < QW3) { split4_store(W2, (uint16_t*)d_W2H, (uint16_t*)d_W2L, i); return; }
    i -= QW3;
    // init: zero wsum/deg/cursor (4 elems per thread)
    *(float4*)(d_wsum + i * 4) = make_float4(0.f, 0.f, 0.f, 0.f);
    *(int4*)(d_deg + i * 4) = make_int4(0, 0, 0, 0);
    *(int4*)(d_cursor + i * 4) = make_int4(0, 0, 0, 0);
}

// ---------------- pipelined split-bf16 GEMM with fused column stats ----------------
// C[M,N] = (Ah+Al)@(Bh+Bl) (drops Al*Bl). grid=(ceil(M/128), N/128), block=256.
// Writes per-CTA column partials: partial[bx*1024 + col]=sum, [bx*1024+512+col]=sumsq.
#define KC 32
#define A_STRIDE 40
#define B_STRIDE 136
__global__ __launch_bounds__(256, 2)
void k_mma(const __nv_bfloat16* __restrict__ Ah, const __nv_bfloat16* __restrict__ Al,
           const __nv_bfloat16* __restrict__ Bh, const __nv_bfloat16* __restrict__ Bl,
           float* __restrict__ C, float* __restrict__ partial, int M, int N, int K) {
    __shared__ __align__(16) uint16_t sA[2][128 * A_STRIDE];
    __shared__ __align__(16) uint16_t sB[2][KC * B_STRIDE];
    __shared__ float sS[8][32], sS2[8][32];
    int tid = threadIdx.x, wid = tid >> 5, lane = tid & 31;
    int bm = blockIdx.x * 128, bn = blockIdx.y * 128;
    int wm = (wid & 1) * 64, wn = (wid >> 1) * 32;
    int mat = lane >> 3, r = lane & 7;
    int kpt = K >> 5;
    int nch = 3 * kpt;

    float acc[4][4][4];
    #pragma unroll
    for (int i = 0; i < 4; i++)
        #pragma unroll
        for (int j = 0; j < 4; j++)
            #pragma unroll
            for (int v = 0; v < 4; v++) acc[i][j][v] = 0.f;

    uint32_t aBase[2] = { smem_u32(sA[0]), smem_u32(sA[1]) };
    uint32_t bBase[2] = { smem_u32(sB[0]), smem_u32(sB[1]) };

    auto issue = [&](int c, int buf) {
        int term = c / kpt;
        int koff = (c - term * kpt) << 5;
        const __nv_bfloat16* Ap = (term < 2) ? Ah : Al;
        const __nv_bfloat16* Bp = (term == 1) ? Bl : Bh;
        #pragma unroll
        for (int i = 0; i < 2; i++) {
            int seg = i * 256 + tid;
            int row = seg >> 2, cs = (seg & 3) << 3;
            cpa16(aBase[buf] + (row * A_STRIDE + cs) * 2,
                  Ap + (size_t)(bm + row) * K + koff + cs, (bm + row) < M);
        }
        #pragma unroll
        for (int i = 0; i < 2; i++) {
            int seg = i * 256 + tid;
            int row = seg >> 4, cs = (seg & 15) << 3;
            cpa16(bBase[buf] + (row * B_STRIDE + cs) * 2,
                  Bp + (size_t)(koff + row) * N + bn + cs, 1);
        }
        asm volatile("cp.async.commit_group;" ::: "memory");
    };

    issue(0, 0);
    for (int c = 0; c < nch; c++) {
        int buf = c & 1;
        if (c + 1 < nch) {
            issue(c + 1, buf ^ 1);
            asm volatile("cp.async.wait_group 1;" ::: "memory");
        } else {
            asm volatile("cp.async.wait_group 0;" ::: "memory");
        }
        __syncthreads();
        #pragma unroll
        for (int ks = 0; ks < KC / 16; ks++) {
            uint32_t a[4][4], b[4][2];
            #pragma unroll
            for (int mt = 0; mt < 4; mt++) {
                int mrow = wm + mt * 16 + (mat & 1) * 8 + r;
                int kcol = ks * 16 + (mat >> 1) * 8;
                ldsm_x4(a[mt][0], a[mt][1], a[mt][2], a[mt][3],
                        aBase[buf] + (mrow * A_STRIDE + kcol) * 2);
            }
            #pragma unroll
            for (int nt = 0; nt < 2; nt++) {
                int krow = ks * 16 + (mat & 1) * 8 + r;
                int ncol = wn + nt * 16 + (mat >> 1) * 8;
                ldsm_x4_t(b[nt * 2][0], b[nt * 2][1], b[nt * 2 + 1][0], b[nt * 2 + 1][1],
                          bBase[buf] + (krow * B_STRIDE + ncol) * 2);
            }
            #pragma unroll
            for (int mt = 0; mt < 4; mt++)
                #pragma unroll
                for (int nt = 0; nt < 4; nt++)
                    mma_bf16(acc[mt][nt], a[mt], b[nt]);
        }
        __syncthreads();
    }

    // store C
    int g = lane >> 2, tg = lane & 3;
    #pragma unroll
    for (int mt = 0; mt < 4; mt++) {
        #pragma unroll
        for (int nt = 0; nt < 4; nt++) {
            int row0 = bm + wm + mt * 16 + g;
            int col = bn + wn + nt * 8 + tg * 2;
            if (row0 < M) {
                C[(size_t)row0 * N + col] = acc[mt][nt][0];
                C[(size_t)row0 * N + col + 1] = acc[mt][nt][1];
            }
            int row1 = row0 + 8;
            if (row1 < M) {
                C[(size_t)row1 * N + col] = acc[mt][nt][2];
                C[(size_t)row1 * N + col + 1] = acc[mt][nt][3];
            }
        }
    }

    // fused column stats: rows >= M contributed exact zeros (A tile zero-filled)
    #pragma unroll
    for (int nt = 0; nt < 4; nt++) {
        #pragma unroll
        for (int p = 0; p < 2; p++) {
            float ss = 0.f, qq = 0.f;
            #pragma unroll
            for (int mt = 0; mt < 4; mt++) {
                float a0 = acc[mt][nt][p], a1 = acc[mt][nt][p + 2];
                ss += a0 + a1;
                qq += a0 * a0 + a1 * a1;
            }
            #pragma unroll
            for (int off = 16; off >= 4; off >>= 1) {
                ss += __shfl_down_sync(0xffffffff, ss, off);
                qq += __shfl_down_sync(0xffffffff, qq, off);
            }
            if (g == 0) {  // lanes 0..3
                sS[wid][nt * 8 + tg * 2 + p] = ss;
                sS2[wid][nt * 8 + tg * 2 + p] = qq;
            }
        }
    }
    __syncthreads();
    if (tid < 128) {
        int w0 = (tid >> 5) * 2, lc = tid & 31;
        float ss = sS[w0][lc] + sS[w0 + 1][lc];
        float qq = sS2[w0][lc] + sS2[w0 + 1][lc];
        partial[blockIdx.x * 1024 + bn + tid] = ss;
        partial[blockIdx.x * 1024 + 512 + bn + tid] = qq;
    }
}

// ---------------- edge weights + degree histogram ----------------
__global__ void k_edge(const float4* __restrict__ ref_bxyz,
                       const float4* __restrict__ query_bxyz,
                       const int* __restrict__ e_ref,
                       const int* __restrict__ e_query) {
    int e = blockIdx.x * blockDim.x + threadIdx.x;
    if (e >= NEDGE) return;
    int r = e_ref[e], q = e_query[e];
    float4 rb = ref_bxyz[r];
    float4 qb = query_bxyz[q];
    float dx = rb.y - qb.y, dy = rb.z - qb.z, dz = rb.w - qb.w;
    float dist = sqrtf(dx * dx + dy * dy + dz * dz);
    float w = 1.0f / (dist + 1e-8f);
    d_w[e] = w;
    atomicAdd(&d_wsum[q], w);
    atomicAdd(&d_deg[q], 1);
}

// ---------------- single-pass scan ----------------
__global__ void k_scan() {
    __shared__ int wsum[32];
    const int CH = 25;
    int tid = threadIdx.x, lane = tid & 31, wid = tid >> 5;
    int base = tid * CH;
    int s = 0;
    #pragma unroll
    for (int i = 0; i < CH; i++) {
        int idx = base + i;
        if (idx < N_QP) s += d_deg[idx];
    }
    int v = s;
    #pragma unroll
    for (int off = 1; off < 32; off <<= 1) {
        int t = __shfl_up_sync(0xffffffff, v, off);
        if (lane >= off) v += t;
    }
    if (lane == 31) wsum[wid] = v;
    __syncthreads();
    if (wid == 0) {
        int w = wsum[lane];
        #pragma unroll
        for (int off = 1; off < 32; off <<= 1) {
            int t = __shfl_up_sync(0xffffffff, w, off);
            if (lane >= off) w += t;
        }
        wsum[lane] = w;
    }
    __syncthreads();
    int warp_excl = (wid == 0) ? 0 : wsum[wid - 1];
    int run = warp_excl + v - s;
    #pragma unroll
    for (int i = 0; i < CH; i++) {
        int idx = base + i;
        if (idx < N_QP) { d_rowstart[idx] = run; run += d_deg[idx]; }
    }
    if (base < N_QP && base + CH >= N_QP) d_rowstart[N_QP] = run;
}

// ---------------- bucket-fill: store (ref_idx, weight) per slot ----------------
__global__ void k_fill(const int* __restrict__ e_query, const int* __restrict__ e_ref) {
    int e = blockIdx.x * blockDim.x + threadIdx.x;
    if (e >= NEDGE) return;
    int q = e_query[e];
    int pos = atomicAdd(&d_cursor[q], 1) + d_rowstart[q];
    d_rsorted[pos] = e_ref[e];
    d_wsorted[pos] = d_w[e];
}

// ---------------- BN finalize from GEMM partials ----------------
__global__ void k_bnfinal(int C, int M, int NBLK,
                          const float* __restrict__ g, const float* __restrict__ b) {
    int c = threadIdx.x;
    if (c >= C) return;
    float s = 0.f, s2 = 0.f;
    for (int bx = 0; bx < NBLK; bx++) {
        s += d_partial[bx * 1024 + c];
        s2 += d_partial[bx * 1024 + 512 + c];
    }
    float m = s / (float)M;
    float v = s2 / (float)M - m * m;
    float a = g[c] * rsqrtf(v + BN_EPS);
    d_bna[c] = a;
    d_bnc[c] = b[c] - a * m;
}

// ---------------- per-query gather ----------------
__global__ void k_gather() {
    int q = blockIdx.x;
    int c = threadIdx.x;
    int s = d_rowstart[q], t = d_rowstart[q + 1];
    float acc = 0.f;
    for (int i = s; i < t; i++) {
        int r = d_rsorted[i];
        acc = fmaf(d_wsorted[i], d_Y1[(size_t)r * C0 + c], acc);
    }
    float outv = 0.f;
    if (t > s) outv = d_bna[c] * acc * (1.0f / d_wsum[q]) + d_bnc[c];
    d_QF[(size_t)q * C0 + c] = outv;
}

// ---------------- x0 = relu(qf + BN(S)), emit split bf16 (float4) ----------------
__global__ void k_x0() {
    int qd = blockIdx.x * blockDim.x + threadIdx.x;
    if (qd >= N_QP * C0 / 4) return;
    int i = qd * 4;
    int c = i & (C0 - 1);
    float4 qf = *(float4*)(d_QF + i);
    float4 sv = *(float4*)(d_S + i);
    float v0 = fmaxf(qf.x + d_bna[c] * sv.x + d_bnc[c], 0.f);
    float v1 = fmaxf(qf.y + d_bna[c + 1] * sv.y + d_bnc[c + 1], 0.f);
    float v2 = fmaxf(qf.z + d_bna[c + 2] * sv.z + d_bnc[c + 2], 0.f);
    float v3 = fmaxf(qf.w + d_bna[c + 3] * sv.w + d_bnc[c + 3], 0.f);
    uint16_t h[4], l[4];
    split2(v0, h[0], l[0]); split2(v1, h[1], l[1]);
    split2(v2, h[2], l[2]); split2(v3, h[3], l[3]);
    *(uint2*)((uint16_t*)d_X0H + i) = make_uint2(h[0] | ((uint32_t)h[1] << 16), h[2] | ((uint32_t)h[3] << 16));
    *(uint2*)((uint16_t*)d_X0L + i) = make_uint2(l[0] | ((uint32_t)l[1] << 16), l[2] | ((uint32_t)l[3] << 16));
}

// ---------------- x1 = relu(a*Y + c), emit split bf16 (C=256, float4) ----------------
__global__ void k_bnrelu_split(const float* __restrict__ Y, int n4) {
    int qd = blockIdx.x * blockDim.x + threadIdx.x;
    if (qd >= n4) return;
    int i = qd * 4;
    int c = i & 255;
    float4 y = *(float4*)(Y + i);
    float v0 = fmaxf(d_bna[c] * y.x + d_bnc[c], 0.f);
    float v1 = fmaxf(d_bna[c + 1] * y.y + d_bnc[c + 1], 0.f);
    float v2 = fmaxf(d_bna[c + 2] * y.z + d_bnc[c + 2], 0.f);
    float v3 = fmaxf(d_bna[c + 3] * y.w + d_bnc[c + 3], 0.f);
    uint16_t h[4], l[4];
    split2(v0, h[0], l[0]); split2(v1, h[1], l[1]);
    split2(v2, h[2], l[2]); split2(v3, h[3], l[3]);
    *(uint2*)((uint16_t*)d_X1H + i) = make_uint2(h[0] | ((uint32_t)h[1] << 16), h[2] | ((uint32_t)h[3] << 16));
    *(uint2*)((uint16_t*)d_X1L + i) = make_uint2(l[0] | ((uint32_t)l[1] << 16), l[2] | ((uint32_t)l[3] << 16));
}

// ---------------- out = relu(a*Y + c) fp32 (C=256, float4) ----------------
__global__ void k_bnrelu_out(const float* __restrict__ Y, float* __restrict__ X, int n4) {
    int qd = blockIdx.x * blockDim.x + threadIdx.x;
    if (qd >= n4) return;
    int i = qd * 4;
    int c = i & 255;
    float4 y = *(float4*)(Y + i);
    float4 o;
    o.x = fmaxf(d_bna[c] * y.x + d_bnc[c], 0.f);
    o.y = fmaxf(d_bna[c + 1] * y.y + d_bnc[c + 1], 0.f);
    o.z = fmaxf(d_bna[c + 2] * y.z + d_bnc[c + 2], 0.f);
    o.w = fmaxf(d_bna[c + 3] * y.w + d_bnc[c + 3], 0.f);
    *(float4*)(X + i) = o;
}

// ---------------- launcher ----------------
extern "C" void kernel_launch(void* const* d_in, const int* in_sizes, int n_in,
                              void* d_out, int out_size) {
    const float* ref_bxyz   = (const float*)d_in[0];
    const float* ref_feat   = (const float*)d_in[1];
    const float* query_bxyz = (const float*)d_in[2];
    const float* query_feat = (const float*)d_in[3];
    const int*   e_ref      = (const int*)d_in[4];
    const int*   e_query    = (const int*)d_in[5];
    const float* Wf0   = (const float*)d_in[6];
    const float* gf0   = (const float*)d_in[7];
    const float* bf0   = (const float*)d_in[8];
    const float* Ws0   = (const float*)d_in[9];
    const float* gs0   = (const float*)d_in[10];
    const float* bs0   = (const float*)d_in[11];
    const float* W1    = (const float*)d_in[12];
    const float* g1    = (const float*)d_in[14];
    const float* beta1 = (const float*)d_in[15];
    const float* W2    = (const float*)d_in[16];
    const float* g2    = (const float*)d_in[18];
    const float* beta2 = (const float*)d_in[19];
    float* out = (float*)d_out;

    float *pY1, *pS, *pY2, *pY3, *pPart;
    cudaGetSymbolAddress((void**)&pY1, d_Y1);
    cudaGetSymbolAddress((void**)&pS,  d_S);
    cudaGetSymbolAddress((void**)&pY2, d_Y2);
    cudaGetSymbolAddress((void**)&pY3, d_Y3);
    cudaGetSymbolAddress((void**)&pPart, d_partial);
    __nv_bfloat16 *pRefH, *pRefL, *pQH, *pQL, *pX0H, *pX0L, *pX1H, *pX1L;
    __nv_bfloat16 *pWf0H, *pWf0L, *pWs0H, *pWs0L, *pW1H, *pW1L, *pW2H, *pW2L;
    cudaGetSymbolAddress((void**)&pRefH, d_refH); cudaGetSymbolAddress((void**)&pRefL, d_refL);
    cudaGetSymbolAddress((void**)&pQH, d_qH);     cudaGetSymbolAddress((void**)&pQL, d_qL);
    cudaGetSymbolAddress((void**)&pX0H, d_X0H);   cudaGetSymbolAddress((void**)&pX0L, d_X0L);
    cudaGetSymbolAddress((void**)&pX1H, d_X1H);   cudaGetSymbolAddress((void**)&pX1L, d_X1L);
    cudaGetSymbolAddress((void**)&pWf0H, d_Wf0H); cudaGetSymbolAddress((void**)&pWf0L, d_Wf0L);
    cudaGetSymbolAddress((void**)&pWs0H, d_Ws0H); cudaGetSymbolAddress((void**)&pWs0L, d_Ws0L);
    cudaGetSymbolAddress((void**)&pW1H, d_W1H);   cudaGetSymbolAddress((void**)&pW1L, d_W1L);
    cudaGetSymbolAddress((void**)&pW2H, d_W2H);   cudaGetSymbolAddress((void**)&pW2L, d_W2L);

    // 1: all conversions + init
    k_split_all<<<(QTOT + 255) / 256, 256>>>(ref_feat, query_feat, Wf0, Ws0, W1, W2);
    // 2-4: edge preprocessing
    k_edge<<<(NEDGE + 255) / 256, 256>>>((const float4*)ref_bxyz, (const float4*)query_bxyz,
                                         e_ref, e_query);
    k_scan<<<1, 1024>>>();
    k_fill<<<(NEDGE + 255) / 256, 256>>>(e_query, e_ref);

    // 5-6: Y1 = ref_feat @ Wf0 (+stats), BN finalize
    {
        dim3 g((N_REFP + 127) / 128, 1);
        k_mma<<<g, 256>>>(pRefH, pRefL, pWf0H, pWf0L, pY1, pPart, N_REFP, C0, C0);
        k_bnfinal<<<1, 256>>>(C0, N_REFP, g.x, gf0, bf0);
    }
    // 7: gather (applies ref BN)
    k_gather<<<N_QP, C0>>>();

    // 8-9: skip branch
    {
        dim3 g((N_QP + 127) / 128, 1);
        k_mma<<<g, 256>>>(pQH, pQL, pWs0H, pWs0L, pS, pPart, N_QP, C0, C0);
        k_bnfinal<<<1, 256>>>(C0, N_QP, g.x, gs0, bs0);
    }
    // 10: x0
    k_x0<<<(N_QP * C0 / 4 + 255) / 256, 256>>>();

    // 11-13: stage 1 (b1 absorbed by BN)
    {
        dim3 g((N_QP + 127) / 128, 2);
        k_mma<<<g, 256>>>(pX0H, pX0L, pW1H, pW1L, pY2, pPart, N_QP, C1, C0);
        k_bnfinal<<<1, 256>>>(C1, N_QP, g.x, g1, beta1);
    }
    k_bnrelu_split<<<(N_QP * C1 / 4 + 255) / 256, 256>>>(pY2, N_QP * C1 / 4);

    // 14-16: stage 2 (b2 absorbed by BN)
    {
        dim3 g((N_QP + 127) / 128, 2);
        k_mma<<<g, 256>>>(pX1H, pX1L, pW2H, pW2L, pY3, pPart, N_QP, C1, C1);
        k_bnfinal<<<1, 256>>>(C1, N_QP, g.x, g2, beta2);
    }
    k_bnrelu_out<<<(N_QP * C1 / 4 + 255) / 256, 256>>>(pY3, out, N_QP * C1 / 4);
}

// round 10
// speedup vs baseline: 2.4328x; 1.2044x over previous
#include <cuda_runtime.h>
#include <cuda_bf16.h>
#include <math.h>
#include <cstdint>

#define N_QP   25000
#define N_REFP 50000
#define NEDGE  400000
#define C0     128
#define C1     256
#define BN_EPS 1e-5f

// ---------------- scratch ----------------
__device__ float d_w[NEDGE];
__device__ float d_wsum[N_QP];
__device__ int   d_deg[N_QP];
__device__ int   d_cursor[N_QP];
__device__ int   d_rowstart[N_QP + 1];
__device__ int   d_rsorted[NEDGE];
__device__ float d_wsorted[NEDGE];
__device__ float d_Y1[(size_t)N_REFP * C0];
__device__ float d_QF[(size_t)N_QP * C0];
__device__ float d_S [(size_t)N_QP * C0];
__device__ float d_Y2[(size_t)N_QP * C1];
__device__ float d_Y3[(size_t)N_QP * C1];
__device__ float d_partial[600 * 1024];      // region A @0 (<=391 CTAs), region B @400*1024
__device__ float d_bn[4][2][256];            // per-stage BN affine params [stage][a/c][col]
__device__ __nv_bfloat16 d_refH[(size_t)N_REFP * C0], d_refL[(size_t)N_REFP * C0];
__device__ __nv_bfloat16 d_qH[(size_t)N_QP * C0],     d_qL[(size_t)N_QP * C0];
__device__ __nv_bfloat16 d_X0H[(size_t)N_QP * C0],    d_X0L[(size_t)N_QP * C0];
__device__ __nv_bfloat16 d_X1H[(size_t)N_QP * C1],    d_X1L[(size_t)N_QP * C1];
__device__ __nv_bfloat16 d_Wf0H[C0 * C0], d_Wf0L[C0 * C0];
__device__ __nv_bfloat16 d_Ws0H[C0 * C0], d_Ws0L[C0 * C0];
__device__ __nv_bfloat16 d_W1H[C0 * C1],  d_W1L[C0 * C1];
__device__ __nv_bfloat16 d_W2H[C1 * C1],  d_W2L[C1 * C1];

// ======================= helpers =======================
__device__ __forceinline__ uint32_t smem_u32(const void* p) {
    uint32_t a;
    asm("{ .reg .u64 t; cvta.to.shared.u64 t, %1; cvt.u32.u64 %0, t; }" : "=r"(a) : "l"(p));
    return a;
}
__device__ __forceinline__ void ldsm_x4(uint32_t& r0, uint32_t& r1, uint32_t& r2, uint32_t& r3,
                                        uint32_t addr) {
    asm volatile("ldmatrix.sync.aligned.m8n8.x4.shared.b16 {%0,%1,%2,%3}, [%4];"
                 : "=r"(r0), "=r"(r1), "=r"(r2), "=r"(r3) : "r"(addr));
}
__device__ __forceinline__ void ldsm_x4_t(uint32_t& r0, uint32_t& r1, uint32_t& r2, uint32_t& r3,
                                          uint32_t addr) {
    asm volatile("ldmatrix.sync.aligned.m8n8.x4.trans.shared.b16 {%0,%1,%2,%3}, [%4];"
                 : "=r"(r0), "=r"(r1), "=r"(r2), "=r"(r3) : "r"(addr));
}
__device__ __forceinline__ void mma_bf16(float* c, const uint32_t* a, const uint32_t* b) {
    asm volatile(
        "mma.sync.aligned.m16n8k16.row.col.f32.bf16.bf16.f32 "
        "{%0,%1,%2,%3}, {%4,%5,%6,%7}, {%8,%9}, {%0,%1,%2,%3};"
        : "+f"(c[0]), "+f"(c[1]), "+f"(c[2]), "+f"(c[3])
        : "r"(a[0]), "r"(a[1]), "r"(a[2]), "r"(a[3]), "r"(b[0]), "r"(b[1]));
}
__device__ __forceinline__ void cpa16(uint32_t dst, const void* src, int valid) {
    asm volatile("cp.async.cg.shared.global [%0], [%1], 16, %2;"
                 :: "r"(dst), "l"(src), "r"(valid ? 16 : 0) : "memory");
}
__device__ __forceinline__ void split2(float v, uint16_t& h, uint16_t& l) {
    __nv_bfloat16 bh = __float2bfloat16(v);
    __nv_bfloat16 bl = __float2bfloat16(v - __bfloat162float(bh));
    h = *(uint16_t*)&bh; l = *(uint16_t*)&bl;
}
__device__ __forceinline__ void split4_store(const float* X, uint16_t* H, uint16_t* L, int q) {
    float4 v = *(const float4*)(X + q * 4);
    uint16_t h[4], l[4];
    split2(v.x, h[0], l[0]); split2(v.y, h[1], l[1]);
    split2(v.z, h[2], l[2]); split2(v.w, h[3], l[3]);
    *(uint2*)(H + q * 4) = make_uint2(h[0] | ((uint32_t)h[1] << 16), h[2] | ((uint32_t)h[3] << 16));
    *(uint2*)(L + q * 4) = make_uint2(l[0] | ((uint32_t)l[1] << 16), l[2] | ((uint32_t)l[3] << 16));
}

// ---------------- mega split: all fp32->split-bf16 conversions ----------------
#define QR  1600000
#define QQ  800000
#define QW0 4096
#define QW1 4096
#define QW2 8192
#define QW3 16384
#define QTOT (QR + QQ + QW0 + QW1 + QW2 + QW3)
__global__ void k_split_all(const float* __restrict__ ref, const float* __restrict__ qf,
                            const float* __restrict__ Wf0, const float* __restrict__ Ws0,
                            const float* __restrict__ W1, const float* __restrict__ W2) {
    int i = blockIdx.x * blockDim.x + threadIdx.x;
    if (i >= QTOT) return;
    if (i < QR) { split4_store(ref, (uint16_t*)d_refH, (uint16_t*)d_refL, i); return; }
    i -= QR;
    if (i < QQ) { split4_store(qf, (uint16_t*)d_qH, (uint16_t*)d_qL, i); return; }
    i -= QQ;
    if (i < QW0) { split4_store(Wf0, (uint16_t*)d_Wf0H, (uint16_t*)d_Wf0L, i); return; }
    i -= QW0;
    if (i < QW1) { split4_store(Ws0, (uint16_t*)d_Ws0H, (uint16_t*)d_Ws0L, i); return; }
    i -= QW1;
    if (i < QW2) { split4_store(W1, (uint16_t*)d_W1H, (uint16_t*)d_W1L, i); return; }
    i -= QW2;
    split4_store(W2, (uint16_t*)d_W2H, (uint16_t*)d_W2L, i);
}

// ---------------- init ----------------
__global__ void k_init() {
    int i = blockIdx.x * blockDim.x + threadIdx.x;
    if (i >= N_QP / 4 + 1) return;
    if (i * 4 + 3 < N_QP) {
        *(float4*)(d_wsum + i * 4) = make_float4(0.f, 0.f, 0.f, 0.f);
        *(int4*)(d_deg + i * 4) = make_int4(0, 0, 0, 0);
        *(int4*)(d_cursor + i * 4) = make_int4(0, 0, 0, 0);
    } else {
        for (int j = i * 4; j < N_QP; j++) { d_wsum[j] = 0.f; d_deg[j] = 0; d_cursor[j] = 0; }
    }
}

// ---------------- pipelined split-bf16 GEMM with fused column stats ----------------
#define KC 32
#define A_STRIDE 40
#define B_STRIDE 136
__global__ __launch_bounds__(256, 2)
void k_mma(const __nv_bfloat16* __restrict__ Ah, const __nv_bfloat16* __restrict__ Al,
           const __nv_bfloat16* __restrict__ Bh, const __nv_bfloat16* __restrict__ Bl,
           float* __restrict__ C, float* __restrict__ partial, int M, int N, int K) {
    __shared__ __align__(16) uint16_t sA[2][128 * A_STRIDE];
    __shared__ __align__(16) uint16_t sB[2][KC * B_STRIDE];
    __shared__ float sS[8][32], sS2[8][32];
    int tid = threadIdx.x, wid = tid >> 5, lane = tid & 31;
    int bm = blockIdx.x * 128, bn = blockIdx.y * 128;
    int wm = (wid & 1) * 64, wn = (wid >> 1) * 32;
    int mat = lane >> 3, r = lane & 7;
    int kpt = K >> 5;
    int nch = 3 * kpt;

    float acc[4][4][4];
    #pragma unroll
    for (int i = 0; i < 4; i++)
        #pragma unroll
        for (int j = 0; j < 4; j++)
            #pragma unroll
            for (int v = 0; v < 4; v++) acc[i][j][v] = 0.f;

    uint32_t aBase[2] = { smem_u32(sA[0]), smem_u32(sA[1]) };
    uint32_t bBase[2] = { smem_u32(sB[0]), smem_u32(sB[1]) };

    auto issue = [&](int c, int buf) {
        int term = c / kpt;
        int koff = (c - term * kpt) << 5;
        const __nv_bfloat16* Ap = (term < 2) ? Ah : Al;
        const __nv_bfloat16* Bp = (term == 1) ? Bl : Bh;
        #pragma unroll
        for (int i = 0; i < 2; i++) {
            int seg = i * 256 + tid;
            int row = seg >> 2, cs = (seg & 3) << 3;
            cpa16(aBase[buf] + (row * A_STRIDE + cs) * 2,
                  Ap + (size_t)(bm + row) * K + koff + cs, (bm + row) < M);
        }
        #pragma unroll
        for (int i = 0; i < 2; i++) {
            int seg = i * 256 + tid;
            int row = seg >> 4, cs = (seg & 15) << 3;
            cpa16(bBase[buf] + (row * B_STRIDE + cs) * 2,
                  Bp + (size_t)(koff + row) * N + bn + cs, 1);
        }
        asm volatile("cp.async.commit_group;" ::: "memory");
    };

    issue(0, 0);
    for (int c = 0; c < nch; c++) {
        int buf = c & 1;
        if (c + 1 < nch) {
            issue(c + 1, buf ^ 1);
            asm volatile("cp.async.wait_group 1;" ::: "memory");
        } else {
            asm volatile("cp.async.wait_group 0;" ::: "memory");
        }
        __syncthreads();
        #pragma unroll
        for (int ks = 0; ks < KC / 16; ks++) {
            uint32_t a[4][4], b[4][2];
            #pragma unroll
            for (int mt = 0; mt < 4; mt++) {
                int mrow = wm + mt * 16 + (mat & 1) * 8 + r;
                int kcol = ks * 16 + (mat >> 1) * 8;
                ldsm_x4(a[mt][0], a[mt][1], a[mt][2], a[mt][3],
                        aBase[buf] + (mrow * A_STRIDE + kcol) * 2);
            }
            #pragma unroll
            for (int nt = 0; nt < 2; nt++) {
                int krow = ks * 16 + (mat & 1) * 8 + r;
                int ncol = wn + nt * 16 + (mat >> 1) * 8;
                ldsm_x4_t(b[nt * 2][0], b[nt * 2][1], b[nt * 2 + 1][0], b[nt * 2 + 1][1],
                          bBase[buf] + (krow * B_STRIDE + ncol) * 2);
            }
            #pragma unroll
            for (int mt = 0; mt < 4; mt++)
                #pragma unroll
                for (int nt = 0; nt < 4; nt++)
                    mma_bf16(acc[mt][nt], a[mt], b[nt]);
        }
        __syncthreads();
    }

    int g = lane >> 2, tg = lane & 3;
    #pragma unroll
    for (int mt = 0; mt < 4; mt++) {
        #pragma unroll
        for (int nt = 0; nt < 4; nt++) {
            int row0 = bm + wm + mt * 16 + g;
            int col = bn + wn + nt * 8 + tg * 2;
            if (row0 < M) {
                C[(size_t)row0 * N + col] = acc[mt][nt][0];
                C[(size_t)row0 * N + col + 1] = acc[mt][nt][1];
            }
            int row1 = row0 + 8;
            if (row1 < M) {
                C[(size_t)row1 * N + col] = acc[mt][nt][2];
                C[(size_t)row1 * N + col + 1] = acc[mt][nt][3];
            }
        }
    }

    // fused column stats (rows >= M contributed exact zeros)
    #pragma unroll
    for (int nt = 0; nt < 4; nt++) {
        #pragma unroll
        for (int p = 0; p < 2; p++) {
            float ss = 0.f, qq = 0.f;
            #pragma unroll
            for (int mt = 0; mt < 4; mt++) {
                float a0 = acc[mt][nt][p], a1 = acc[mt][nt][p + 2];
                ss += a0 + a1;
                qq += a0 * a0 + a1 * a1;
            }
            #pragma unroll
            for (int off = 16; off >= 4; off >>= 1) {
                ss += __shfl_down_sync(0xffffffff, ss, off);
                qq += __shfl_down_sync(0xffffffff, qq, off);
            }
            if (g == 0) {
                sS[wid][nt * 8 + tg * 2 + p] = ss;
                sS2[wid][nt * 8 + tg * 2 + p] = qq;
            }
        }
    }
    __syncthreads();
    if (tid < 128) {
        int w0 = (tid >> 5) * 2, lc = tid & 31;
        partial[blockIdx.x * 1024 + bn + tid] = sS[w0][lc] + sS[w0 + 1][lc];
        partial[blockIdx.x * 1024 + 512 + bn + tid] = sS2[w0][lc] + sS2[w0 + 1][lc];
    }
}

// ---------------- edge weights + degree histogram ----------------
__global__ void k_edge(const float4* __restrict__ ref_bxyz,
                       const float4* __restrict__ query_bxyz,
                       const int* __restrict__ e_ref,
                       const int* __restrict__ e_query) {
    int e = blockIdx.x * blockDim.x + threadIdx.x;
    if (e >= NEDGE) return;
    int r = e_ref[e], q = e_query[e];
    float4 rb = ref_bxyz[r];
    float4 qb = query_bxyz[q];
    float dx = rb.y - qb.y, dy = rb.z - qb.z, dz = rb.w - qb.w;
    float dist = sqrtf(dx * dx + dy * dy + dz * dz);
    float w = 1.0f / (dist + 1e-8f);
    d_w[e] = w;
    atomicAdd(&d_wsum[q], w);
    atomicAdd(&d_deg[q], 1);
}

// ---------------- single-pass scan ----------------
__global__ void k_scan() {
    __shared__ int wsum[32];
    const int CH = 25;
    int tid = threadIdx.x, lane = tid & 31, wid = tid >> 5;
    int base = tid * CH;
    int s = 0;
    #pragma unroll
    for (int i = 0; i < CH; i++) {
        int idx = base + i;
        if (idx < N_QP) s += d_deg[idx];
    }
    int v = s;
    #pragma unroll
    for (int off = 1; off < 32; off <<= 1) {
        int t = __shfl_up_sync(0xffffffff, v, off);
        if (lane >= off) v += t;
    }
    if (lane == 31) wsum[wid] = v;
    __syncthreads();
    if (wid == 0) {
        int w = wsum[lane];
        #pragma unroll
        for (int off = 1; off < 32; off <<= 1) {
            int t = __shfl_up_sync(0xffffffff, w, off);
            if (lane >= off) w += t;
        }
        wsum[lane] = w;
    }
    __syncthreads();
    int warp_excl = (wid == 0) ? 0 : wsum[wid - 1];
    int run = warp_excl + v - s;
    #pragma unroll
    for (int i = 0; i < CH; i++) {
        int idx = base + i;
        if (idx < N_QP) { d_rowstart[idx] = run; run += d_deg[idx]; }
    }
    if (base < N_QP && base + CH >= N_QP) d_rowstart[N_QP] = run;
}

// ---------------- bucket-fill: (ref_idx, weight) per slot ----------------
__global__ void k_fill(const int* __restrict__ e_query, const int* __restrict__ e_ref) {
    int e = blockIdx.x * blockDim.x + threadIdx.x;
    if (e >= NEDGE) return;
    int q = e_query[e];
    int pos = atomicAdd(&d_cursor[q], 1) + d_rowstart[q];
    d_rsorted[pos] = e_ref[e];
    d_wsorted[pos] = d_w[e];
}

// ---------------- BN finalize ----------------
__global__ void k_bnfinal(int C, int M, int NBLK, const float* __restrict__ partial,
                          const float* __restrict__ g, const float* __restrict__ b,
                          float* __restrict__ bna, float* __restrict__ bnc) {
    int c = threadIdx.x;
    if (c >= C) return;
    float s = 0.f, s2 = 0.f;
    for (int bx = 0; bx < NBLK; bx++) {
        s += partial[bx * 1024 + c];
        s2 += partial[bx * 1024 + 512 + c];
    }
    float m = s / (float)M;
    float v = s2 / (float)M - m * m;
    float a = g[c] * rsqrtf(v + BN_EPS);
    bna[c] = a;
    bnc[c] = b[c] - a * m;
}

// ---------------- per-query gather: 4 warps x float4 lanes ----------------
__global__ void k_gather(const float* __restrict__ bna, const float* __restrict__ bnc) {
    __shared__ float sPart[4][128];
    int q = blockIdx.x;
    int tid = threadIdx.x, wid = tid >> 5, lane = tid & 31;
    int s = d_rowstart[q], t = d_rowstart[q + 1];
    float4 acc = make_float4(0.f, 0.f, 0.f, 0.f);
    for (int i = s + wid; i < t; i += 4) {
        int r = d_rsorted[i];
        float w = d_wsorted[i];
        float4 y = *(const float4*)(d_Y1 + (size_t)r * C0 + lane * 4);
        acc.x = fmaf(w, y.x, acc.x); acc.y = fmaf(w, y.y, acc.y);
        acc.z = fmaf(w, y.z, acc.z); acc.w = fmaf(w, y.w, acc.w);
    }
    sPart[wid][lane * 4 + 0] = acc.x;
    sPart[wid][lane * 4 + 1] = acc.y;
    sPart[wid][lane * 4 + 2] = acc.z;
    sPart[wid][lane * 4 + 3] = acc.w;
    __syncthreads();
    int c = tid;  // 128 threads
    float sum = sPart[0][c] + sPart[1][c] + sPart[2][c] + sPart[3][c];
    float outv = 0.f;
    if (t > s) outv = bna[c] * sum * (1.0f / d_wsum[q]) + bnc[c];
    d_QF[(size_t)q * C0 + c] = outv;
}

// ---------------- x0 = relu(qf + BN(S)), emit split bf16 ----------------
__global__ void k_x0(const float* __restrict__ bna, const float* __restrict__ bnc) {
    int qd = blockIdx.x * blockDim.x + threadIdx.x;
    if (qd >= N_QP * C0 / 4) return;
    int i = qd * 4;
    int c = i & (C0 - 1);
    float4 qf = *(float4*)(d_QF + i);
    float4 sv = *(float4*)(d_S + i);
    float v0 = fmaxf(qf.x + bna[c] * sv.x + bnc[c], 0.f);
    float v1 = fmaxf(qf.y + bna[c + 1] * sv.y + bnc[c + 1], 0.f);
    float v2 = fmaxf(qf.z + bna[c + 2] * sv.z + bnc[c + 2], 0.f);
    float v3 = fmaxf(qf.w + bna[c + 3] * sv.w + bnc[c + 3], 0.f);
    uint16_t h[4], l[4];
    split2(v0, h[0], l[0]); split2(v1, h[1], l[1]);
    split2(v2, h[2], l[2]); split2(v3, h[3], l[3]);
    *(uint2*)((uint16_t*)d_X0H + i) = make_uint2(h[0] | ((uint32_t)h[1] << 16), h[2] | ((uint32_t)h[3] << 16));
    *(uint2*)((uint16_t*)d_X0L + i) = make_uint2(l[0] | ((uint32_t)l[1] << 16), l[2] | ((uint32_t)l[3] << 16));
}

// ---------------- x1 = relu(a*Y + c), emit split bf16 (C=256) ----------------
__global__ void k_bnrelu_split(const float* __restrict__ Y, int n4,
                               const float* __restrict__ bna, const float* __restrict__ bnc) {
    int qd = blockIdx.x * blockDim.x + threadIdx.x;
    if (qd >= n4) return;
    int i = qd * 4;
    int c = i & 255;
    float4 y = *(float4*)(Y + i);
    float v0 = fmaxf(bna[c] * y.x + bnc[c], 0.f);
    float v1 = fmaxf(bna[c + 1] * y.y + bnc[c + 1], 0.f);
    float v2 = fmaxf(bna[c + 2] * y.z + bnc[c + 2], 0.f);
    float v3 = fmaxf(bna[c + 3] * y.w + bnc[c + 3], 0.f);
    uint16_t h[4], l[4];
    split2(v0, h[0], l[0]); split2(v1, h[1], l[1]);
    split2(v2, h[2], l[2]); split2(v3, h[3], l[3]);
    *(uint2*)((uint16_t*)d_X1H + i) = make_uint2(h[0] | ((uint32_t)h[1] << 16), h[2] | ((uint32_t)h[3] << 16));
    *(uint2*)((uint16_t*)d_X1L + i) = make_uint2(l[0] | ((uint32_t)l[1] << 16), l[2] | ((uint32_t)l[3] << 16));
}

// ---------------- out = relu(a*Y + c) fp32 (C=256) ----------------
__global__ void k_bnrelu_out(const float* __restrict__ Y, float* __restrict__ X, int n4,
                             const float* __restrict__ bna, const float* __restrict__ bnc) {
    int qd = blockIdx.x * blockDim.x + threadIdx.x;
    if (qd >= n4) return;
    int i = qd * 4;
    int c = i & 255;
    float4 y = *(float4*)(Y + i);
    float4 o;
    o.x = fmaxf(bna[c] * y.x + bnc[c], 0.f);
    o.y = fmaxf(bna[c + 1] * y.y + bnc[c + 1], 0.f);
    o.z = fmaxf(bna[c + 2] * y.z + bnc[c + 2], 0.f);
    o.w = fmaxf(bna[c + 3] * y.w + bnc[c + 3], 0.f);
    *(float4*)(X + i) = o;
}

// ---------------- launcher ----------------
extern "C" void kernel_launch(void* const* d_in, const int* in_sizes, int n_in,
                              void* d_out, int out_size) {
    const float* ref_bxyz   = (const float*)d_in[0];
    const float* ref_feat   = (const float*)d_in[1];
    const float* query_bxyz = (const float*)d_in[2];
    const float* query_feat = (const float*)d_in[3];
    const int*   e_ref      = (const int*)d_in[4];
    const int*   e_query    = (const int*)d_in[5];
    const float* Wf0   = (const float*)d_in[6];
    const float* gf0   = (const float*)d_in[7];
    const float* bf0   = (const float*)d_in[8];
    const float* Ws0   = (const float*)d_in[9];
    const float* gs0   = (const float*)d_in[10];
    const float* bs0   = (const float*)d_in[11];
    const float* W1    = (const float*)d_in[12];
    const float* g1    = (const float*)d_in[14];
    const float* beta1 = (const float*)d_in[15];
    const float* W2    = (const float*)d_in[16];
    const float* g2    = (const float*)d_in[18];
    const float* beta2 = (const float*)d_in[19];
    float* out = (float*)d_out;

    float *pY1, *pS, *pY2, *pY3, *pPart, *pBN;
    cudaGetSymbolAddress((void**)&pY1, d_Y1);
    cudaGetSymbolAddress((void**)&pS,  d_S);
    cudaGetSymbolAddress((void**)&pY2, d_Y2);
    cudaGetSymbolAddress((void**)&pY3, d_Y3);
    cudaGetSymbolAddress((void**)&pPart, d_partial);
    cudaGetSymbolAddress((void**)&pBN, d_bn);
    float* pPartA = pPart;
    float* pPartB = pPart + 400 * 1024;
    float* bna0 = pBN;            float* bnc0 = pBN + 256;
    float* bna1 = pBN + 512;      float* bnc1 = pBN + 768;
    float* bna2 = pBN + 1024;     float* bnc2 = pBN + 1280;
    float* bna3 = pBN + 1536;     float* bnc3 = pBN + 1792;

    __nv_bfloat16 *pRefH, *pRefL, *pQH, *pQL, *pX0H, *pX0L, *pX1H, *pX1L;
    __nv_bfloat16 *pWf0H, *pWf0L, *pWs0H, *pWs0L, *pW1H, *pW1L, *pW2H, *pW2L;
    cudaGetSymbolAddress((void**)&pRefH, d_refH); cudaGetSymbolAddress((void**)&pRefL, d_refL);
    cudaGetSymbolAddress((void**)&pQH, d_qH);     cudaGetSymbolAddress((void**)&pQL, d_qL);
    cudaGetSymbolAddress((void**)&pX0H, d_X0H);   cudaGetSymbolAddress((void**)&pX0L, d_X0L);
    cudaGetSymbolAddress((void**)&pX1H, d_X1H);   cudaGetSymbolAddress((void**)&pX1L, d_X1L);
    cudaGetSymbolAddress((void**)&pWf0H, d_Wf0H); cudaGetSymbolAddress((void**)&pWf0L, d_Wf0L);
    cudaGetSymbolAddress((void**)&pWs0H, d_Ws0H); cudaGetSymbolAddress((void**)&pWs0L, d_Ws0L);
    cudaGetSymbolAddress((void**)&pW1H, d_W1H);   cudaGetSymbolAddress((void**)&pW1L, d_W1L);
    cudaGetSymbolAddress((void**)&pW2H, d_W2H);   cudaGetSymbolAddress((void**)&pW2L, d_W2L);

    static cudaStream_t s1 = nullptr, s2 = nullptr;
    static cudaEvent_t evStart, evSplit, evEdge, evS;
    if (!s1) {
        cudaStreamCreateWithFlags(&s1, cudaStreamNonBlocking);
        cudaStreamCreateWithFlags(&s2, cudaStreamNonBlocking);
        cudaEventCreateWithFlags(&evStart, cudaEventDisableTiming);
        cudaEventCreateWithFlags(&evSplit, cudaEventDisableTiming);
        cudaEventCreateWithFlags(&evEdge, cudaEventDisableTiming);
        cudaEventCreateWithFlags(&evS, cudaEventDisableTiming);
    }

    // fork s1: edge preprocessing (independent of splits/GEMMs)
    cudaEventRecord(evStart, 0);
    cudaStreamWaitEvent(s1, evStart, 0);
    k_init<<<(N_QP / 4 + 256) / 256, 256, 0, s1>>>();
    k_edge<<<(NEDGE + 255) / 256, 256, 0, s1>>>((const float4*)ref_bxyz,
                                                (const float4*)query_bxyz, e_ref, e_query);
    k_scan<<<1, 1024, 0, s1>>>();
    k_fill<<<(NEDGE + 255) / 256, 256, 0, s1>>>(e_query, e_ref);
    cudaEventRecord(evEdge, s1);

    // main: conversions
    k_split_all<<<(QTOT + 255) / 256, 256>>>(ref_feat, query_feat, Wf0, Ws0, W1, W2);
    cudaEventRecord(evSplit, 0);

    // fork s2: skip-branch GEMM + its BN finalize (independent of Y1 chain)
    cudaStreamWaitEvent(s2, evSplit, 0);
    {
        dim3 g((N_QP + 127) / 128, 1);
        k_mma<<<g, 256, 0, s2>>>(pQH, pQL, pWs0H, pWs0L, pS, pPartB, N_QP, C0, C0);
        k_bnfinal<<<1, 256, 0, s2>>>(C0, N_QP, g.x, pPartB, gs0, bs0, bna1, bnc1);
    }
    cudaEventRecord(evS, s2);

    // main chain: Y1 GEMM -> BN f0 -> gather -> x0 -> stage1 -> stage2
    {
        dim3 g((N_REFP + 127) / 128, 1);
        k_mma<<<g, 256>>>(pRefH, pRefL, pWf0H, pWf0L, pY1, pPartA, N_REFP, C0, C0);
        k_bnfinal<<<1, 256>>>(C0, N_REFP, g.x, pPartA, gf0, bf0, bna0, bnc0);
    }
    cudaStreamWaitEvent(0, evEdge, 0);
    k_gather<<<N_QP, 128>>>(bna0, bnc0);
    cudaStreamWaitEvent(0, evS, 0);
    k_x0<<<(N_QP * C0 / 4 + 255) / 256, 256>>>(bna1, bnc1);

    {
        dim3 g((N_QP + 127) / 128, 2);
        k_mma<<<g, 256>>>(pX0H, pX0L, pW1H, pW1L, pY2, pPartA, N_QP, C1, C0);
        k_bnfinal<<<1, 256>>>(C1, N_QP, g.x, pPartA, g1, beta1, bna2, bnc2);
    }
    k_bnrelu_split<<<(N_QP * C1 / 4 + 255) / 256, 256>>>(pY2, N_QP * C1 / 4, bna2, bnc2);

    {
        dim3 g((N_QP + 127) / 128, 2);
        k_mma<<<g, 256>>>(pX1H, pX1L, pW2H, pW2L, pY3, pPartA, N_QP, C1, C1);
        k_bnfinal<<<1, 256>>>(C1, N_QP, g.x, pPartA, g2, beta2, bna3, bnc3);
    }
    k_bnrelu_out<<<(N_QP * C1 / 4 + 255) / 256, 256>>>(pY3, out, N_QP * C1 / 4, bna3, bnc3);
}

// round 11
// speedup vs baseline: 2.6875x; 1.1047x over previous
#include <cuda_runtime.h>
#include <cuda_bf16.h>
#include <math.h>
#include <cstdint>

#define N_QP   25000
#define N_REFP 50000
#define NEDGE  400000
#define C0     128
#define C1     256
#define BN_EPS 1e-5f

// ---------------- scratch ----------------
__device__ float d_w[NEDGE];
__device__ float d_wsum[N_QP];
__device__ int   d_deg[N_QP];
__device__ int   d_cursor[N_QP];
__device__ int   d_rowstart[N_QP + 1];
__device__ int   d_rsorted[NEDGE];
__device__ float d_wsorted[NEDGE];
__device__ float d_Y1[(size_t)N_REFP * C0];
__device__ float d_S [(size_t)N_QP * C0];
__device__ float d_Y2[(size_t)N_QP * C1];
__device__ float d_Y3[(size_t)N_QP * C1];
__device__ float d_partial[600 * 1024];      // region A @0 (<=400 CTAs), region B @400*1024
__device__ float d_bn[4][2][256];            // per-stage BN affine [stage][a|c][col]
__device__ __nv_bfloat16 d_refH[(size_t)N_REFP * C0], d_refL[(size_t)N_REFP * C0];
__device__ __nv_bfloat16 d_qH[(size_t)N_QP * C0],     d_qL[(size_t)N_QP * C0];
__device__ __nv_bfloat16 d_X0H[(size_t)N_QP * C0],    d_X0L[(size_t)N_QP * C0];
__device__ __nv_bfloat16 d_X1H[(size_t)N_QP * C1],    d_X1L[(size_t)N_QP * C1];
__device__ __nv_bfloat16 d_Wf0H[C0 * C0], d_Wf0L[C0 * C0];
__device__ __nv_bfloat16 d_Ws0H[C0 * C0], d_Ws0L[C0 * C0];
__device__ __nv_bfloat16 d_W1H[C0 * C1],  d_W1L[C0 * C1];
__device__ __nv_bfloat16 d_W2H[C1 * C1],  d_W2L[C1 * C1];

// ======================= helpers =======================
__device__ __forceinline__ uint32_t smem_u32(const void* p) {
    uint32_t a;
    asm("{ .reg .u64 t; cvta.to.shared.u64 t, %1; cvt.u32.u64 %0, t; }" : "=r"(a) : "l"(p));
    return a;
}
__device__ __forceinline__ void ldsm_x4(uint32_t& r0, uint32_t& r1, uint32_t& r2, uint32_t& r3,
                                        uint32_t addr) {
    asm volatile("ldmatrix.sync.aligned.m8n8.x4.shared.b16 {%0,%1,%2,%3}, [%4];"
                 : "=r"(r0), "=r"(r1), "=r"(r2), "=r"(r3) : "r"(addr));
}
__device__ __forceinline__ void ldsm_x4_t(uint32_t& r0, uint32_t& r1, uint32_t& r2, uint32_t& r3,
                                          uint32_t addr) {
    asm volatile("ldmatrix.sync.aligned.m8n8.x4.trans.shared.b16 {%0,%1,%2,%3}, [%4];"
                 : "=r"(r0), "=r"(r1), "=r"(r2), "=r"(r3) : "r"(addr));
}
__device__ __forceinline__ void mma_bf16(float* c, const uint32_t* a, const uint32_t* b) {
    asm volatile(
        "mma.sync.aligned.m16n8k16.row.col.f32.bf16.bf16.f32 "
        "{%0,%1,%2,%3}, {%4,%5,%6,%7}, {%8,%9}, {%0,%1,%2,%3};"
        : "+f"(c[0]), "+f"(c[1]), "+f"(c[2]), "+f"(c[3])
        : "r"(a[0]), "r"(a[1]), "r"(a[2]), "r"(a[3]), "r"(b[0]), "r"(b[1]));
}
__device__ __forceinline__ void cpa16(uint32_t dst, const void* src, int valid) {
    asm volatile("cp.async.cg.shared.global [%0], [%1], 16, %2;"
                 :: "r"(dst), "l"(src), "r"(valid ? 16 : 0) : "memory");
}
__device__ __forceinline__ void split2(float v, uint16_t& h, uint16_t& l) {
    __nv_bfloat16 bh = __float2bfloat16(v);
    __nv_bfloat16 bl = __float2bfloat16(v - __bfloat162float(bh));
    h = *(uint16_t*)&bh; l = *(uint16_t*)&bl;
}
__device__ __forceinline__ void split4_store(const float* X, uint16_t* H, uint16_t* L, int q) {
    float4 v = *(const float4*)(X + q * 4);
    uint16_t h[4], l[4];
    split2(v.x, h[0], l[0]); split2(v.y, h[1], l[1]);
    split2(v.z, h[2], l[2]); split2(v.w, h[3], l[3]);
    *(uint2*)(H + q * 4) = make_uint2(h[0] | ((uint32_t)h[1] << 16), h[2] | ((uint32_t)h[3] << 16));
    *(uint2*)(L + q * 4) = make_uint2(l[0] | ((uint32_t)l[1] << 16), l[2] | ((uint32_t)l[3] << 16));
}

// ---------------- split kernels ----------------
#define QR  1600000
#define QQ  800000
#define QW0 4096
#define QW1 4096
#define QW2 8192
#define QW3 16384
#define QA_TOT (QR + QW0)
#define QB_TOT (QQ + QW1 + QW2 + QW3)
// critical path: ref_feat + Wf0 only
__global__ void k_split_a(const float* __restrict__ ref, const float* __restrict__ Wf0) {
    int i = blockIdx.x * blockDim.x + threadIdx.x;
    if (i >= QA_TOT) return;
    if (i < QR) { split4_store(ref, (uint16_t*)d_refH, (uint16_t*)d_refL, i); return; }
    i -= QR;
    split4_store(Wf0, (uint16_t*)d_Wf0H, (uint16_t*)d_Wf0L, i);
}
// side stream: query_feat, Ws0, W1, W2
__global__ void k_split_b(const float* __restrict__ qf, const float* __restrict__ Ws0,
                          const float* __restrict__ W1, const float* __restrict__ W2) {
    int i = blockIdx.x * blockDim.x + threadIdx.x;
    if (i >= QB_TOT) return;
    if (i < QQ) { split4_store(qf, (uint16_t*)d_qH, (uint16_t*)d_qL, i); return; }
    i -= QQ;
    if (i < QW1) { split4_store(Ws0, (uint16_t*)d_Ws0H, (uint16_t*)d_Ws0L, i); return; }
    i -= QW1;
    if (i < QW2) { split4_store(W1, (uint16_t*)d_W1H, (uint16_t*)d_W1L, i); return; }
    i -= QW2;
    split4_store(W2, (uint16_t*)d_W2H, (uint16_t*)d_W2L, i);
}

// ---------------- init ----------------
__global__ void k_init() {
    int i = blockIdx.x * blockDim.x + threadIdx.x;
    if (i >= N_QP / 4 + 1) return;
    if (i * 4 + 3 < N_QP) {
        *(float4*)(d_wsum + i * 4) = make_float4(0.f, 0.f, 0.f, 0.f);
        *(int4*)(d_deg + i * 4) = make_int4(0, 0, 0, 0);
        *(int4*)(d_cursor + i * 4) = make_int4(0, 0, 0, 0);
    } else {
        for (int j = i * 4; j < N_QP; j++) { d_wsum[j] = 0.f; d_deg[j] = 0; d_cursor[j] = 0; }
    }
}

// ---------------- pipelined split-bf16 GEMM with fused column stats ----------------
#define KC 32
#define A_STRIDE 40
#define B_STRIDE 136
__global__ __launch_bounds__(256, 2)
void k_mma(const __nv_bfloat16* __restrict__ Ah, const __nv_bfloat16* __restrict__ Al,
           const __nv_bfloat16* __restrict__ Bh, const __nv_bfloat16* __restrict__ Bl,
           float* __restrict__ C, float* __restrict__ partial, int M, int N, int K) {
    __shared__ __align__(16) uint16_t sA[2][128 * A_STRIDE];
    __shared__ __align__(16) uint16_t sB[2][KC * B_STRIDE];
    __shared__ float sS[8][32], sS2[8][32];
    int tid = threadIdx.x, wid = tid >> 5, lane = tid & 31;
    int bm = blockIdx.x * 128, bn = blockIdx.y * 128;
    int wm = (wid & 1) * 64, wn = (wid >> 1) * 32;
    int mat = lane >> 3, r = lane & 7;
    int kpt = K >> 5;
    int nch = 3 * kpt;

    float acc[4][4][4];
    #pragma unroll
    for (int i = 0; i < 4; i++)
        #pragma unroll
        for (int j = 0; j < 4; j++)
            #pragma unroll
            for (int v = 0; v < 4; v++) acc[i][j][v] = 0.f;

    uint32_t aBase[2] = { smem_u32(sA[0]), smem_u32(sA[1]) };
    uint32_t bBase[2] = { smem_u32(sB[0]), smem_u32(sB[1]) };

    auto issue = [&](int c, int buf) {
        int term = c / kpt;
        int koff = (c - term * kpt) << 5;
        const __nv_bfloat16* Ap = (term < 2) ? Ah : Al;
        const __nv_bfloat16* Bp = (term == 1) ? Bl : Bh;
        #pragma unroll
        for (int i = 0; i < 2; i++) {
            int seg = i * 256 + tid;
            int row = seg >> 2, cs = (seg & 3) << 3;
            cpa16(aBase[buf] + (row * A_STRIDE + cs) * 2,
                  Ap + (size_t)(bm + row) * K + koff + cs, (bm + row) < M);
        }
        #pragma unroll
        for (int i = 0; i < 2; i++) {
            int seg = i * 256 + tid;
            int row = seg >> 4, cs = (seg & 15) << 3;
            cpa16(bBase[buf] + (row * B_STRIDE + cs) * 2,
                  Bp + (size_t)(koff + row) * N + bn + cs, 1);
        }
        asm volatile("cp.async.commit_group;" ::: "memory");
    };

    issue(0, 0);
    for (int c = 0; c < nch; c++) {
        int buf = c & 1;
        if (c + 1 < nch) {
            issue(c + 1, buf ^ 1);
            asm volatile("cp.async.wait_group 1;" ::: "memory");
        } else {
            asm volatile("cp.async.wait_group 0;" ::: "memory");
        }
        __syncthreads();
        #pragma unroll
        for (int ks = 0; ks < KC / 16; ks++) {
            uint32_t a[4][4], b[4][2];
            #pragma unroll
            for (int mt = 0; mt < 4; mt++) {
                int mrow = wm + mt * 16 + (mat & 1) * 8 + r;
                int kcol = ks * 16 + (mat >> 1) * 8;
                ldsm_x4(a[mt][0], a[mt][1], a[mt][2], a[mt][3],
                        aBase[buf] + (mrow * A_STRIDE + kcol) * 2);
            }
            #pragma unroll
            for (int nt = 0; nt < 2; nt++) {
                int krow = ks * 16 + (mat & 1) * 8 + r;
                int ncol = wn + nt * 16 + (mat >> 1) * 8;
                ldsm_x4_t(b[nt * 2][0], b[nt * 2][1], b[nt * 2 + 1][0], b[nt * 2 + 1][1],
                          bBase[buf] + (krow * B_STRIDE + ncol) * 2);
            }
            #pragma unroll
            for (int mt = 0; mt < 4; mt++)
                #pragma unroll
                for (int nt = 0; nt < 4; nt++)
                    mma_bf16(acc[mt][nt], a[mt], b[nt]);
        }
        __syncthreads();
    }

    int g = lane >> 2, tg = lane & 3;
    #pragma unroll
    for (int mt = 0; mt < 4; mt++) {
        #pragma unroll
        for (int nt = 0; nt < 4; nt++) {
            int row0 = bm + wm + mt * 16 + g;
            int col = bn + wn + nt * 8 + tg * 2;
            if (row0 < M) {
                C[(size_t)row0 * N + col] = acc[mt][nt][0];
                C[(size_t)row0 * N + col + 1] = acc[mt][nt][1];
            }
            int row1 = row0 + 8;
            if (row1 < M) {
                C[(size_t)row1 * N + col] = acc[mt][nt][2];
                C[(size_t)row1 * N + col + 1] = acc[mt][nt][3];
            }
        }
    }

    // fused column stats (rows >= M contributed exact zeros)
    #pragma unroll
    for (int nt = 0; nt < 4; nt++) {
        #pragma unroll
        for (int p = 0; p < 2; p++) {
            float ss = 0.f, qq = 0.f;
            #pragma unroll
            for (int mt = 0; mt < 4; mt++) {
                float a0 = acc[mt][nt][p], a1 = acc[mt][nt][p + 2];
                ss += a0 + a1;
                qq += a0 * a0 + a1 * a1;
            }
            #pragma unroll
            for (int off = 16; off >= 4; off >>= 1) {
                ss += __shfl_down_sync(0xffffffff, ss, off);
                qq += __shfl_down_sync(0xffffffff, qq, off);
            }
            if (g == 0) {
                sS[wid][nt * 8 + tg * 2 + p] = ss;
                sS2[wid][nt * 8 + tg * 2 + p] = qq;
            }
        }
    }
    __syncthreads();
    if (tid < 128) {
        int w0 = (tid >> 5) * 2, lc = tid & 31;
        partial[blockIdx.x * 1024 + bn + tid] = sS[w0][lc] + sS[w0 + 1][lc];
        partial[blockIdx.x * 1024 + 512 + bn + tid] = sS2[w0][lc] + sS2[w0 + 1][lc];
    }
}

// ---------------- edge weights + degree histogram ----------------
__global__ void k_edge(const float4* __restrict__ ref_bxyz,
                       const float4* __restrict__ query_bxyz,
                       const int* __restrict__ e_ref,
                       const int* __restrict__ e_query) {
    int e = blockIdx.x * blockDim.x + threadIdx.x;
    if (e >= NEDGE) return;
    int r = e_ref[e], q = e_query[e];
    float4 rb = ref_bxyz[r];
    float4 qb = query_bxyz[q];
    float dx = rb.y - qb.y, dy = rb.z - qb.z, dz = rb.w - qb.w;
    float dist = sqrtf(dx * dx + dy * dy + dz * dz);
    float w = 1.0f / (dist + 1e-8f);
    d_w[e] = w;
    atomicAdd(&d_wsum[q], w);
    atomicAdd(&d_deg[q], 1);
}

// ---------------- single-pass scan ----------------
__global__ void k_scan() {
    __shared__ int wsum[32];
    const int CH = 25;
    int tid = threadIdx.x, lane = tid & 31, wid = tid >> 5;
    int base = tid * CH;
    int s = 0;
    #pragma unroll
    for (int i = 0; i < CH; i++) {
        int idx = base + i;
        if (idx < N_QP) s += d_deg[idx];
    }
    int v = s;
    #pragma unroll
    for (int off = 1; off < 32; off <<= 1) {
        int t = __shfl_up_sync(0xffffffff, v, off);
        if (lane >= off) v += t;
    }
    if (lane == 31) wsum[wid] = v;
    __syncthreads();
    if (wid == 0) {
        int w = wsum[lane];
        #pragma unroll
        for (int off = 1; off < 32; off <<= 1) {
            int t = __shfl_up_sync(0xffffffff, w, off);
            if (lane >= off) w += t;
        }
        wsum[lane] = w;
    }
    __syncthreads();
    int warp_excl = (wid == 0) ? 0 : wsum[wid - 1];
    int run = warp_excl + v - s;
    #pragma unroll
    for (int i = 0; i < CH; i++) {
        int idx = base + i;
        if (idx < N_QP) { d_rowstart[idx] = run; run += d_deg[idx]; }
    }
    if (base < N_QP && base + CH >= N_QP) d_rowstart[N_QP] = run;
}

// ---------------- bucket-fill: (ref_idx, weight) per slot ----------------
__global__ void k_fill(const int* __restrict__ e_query, const int* __restrict__ e_ref) {
    int e = blockIdx.x * blockDim.x + threadIdx.x;
    if (e >= NEDGE) return;
    int q = e_query[e];
    int pos = atomicAdd(&d_cursor[q], 1) + d_rowstart[q];
    d_rsorted[pos] = e_ref[e];
    d_wsorted[pos] = d_w[e];
}

// ---------------- BN finalize (parallel, 1024 threads) ----------------
__global__ void k_bnfinal(int C, int M, int NBLK, const float* __restrict__ partial,
                          const float* __restrict__ g, const float* __restrict__ b,
                          float* __restrict__ bna, float* __restrict__ bnc) {
    __shared__ float redS[4][256], redQ[4][256];
    int t = threadIdx.x;
    int c = t & 255, chunk = t >> 8;
    float s = 0.f, s2 = 0.f;
    for (int bx = chunk; bx < NBLK; bx += 4) {
        s += partial[bx * 1024 + c];
        s2 += partial[bx * 1024 + 512 + c];
    }
    redS[chunk][c] = s;
    redQ[chunk][c] = s2;
    __syncthreads();
    if (t < C) {
        float S = redS[0][t] + redS[1][t] + redS[2][t] + redS[3][t];
        float Q = redQ[0][t] + redQ[1][t] + redQ[2][t] + redQ[3][t];
        float m = S / (float)M;
        float v = Q / (float)M - m * m;
        float a = g[t] * rsqrtf(v + BN_EPS);
        bna[t] = a;
        bnc[t] = b[t] - a * m;
    }
}

// ---------------- fused gather + x0: QF, skip-add, BN, relu, split ----------------
__global__ void k_gather_x0(const float* __restrict__ bna0, const float* __restrict__ bnc0,
                            const float* __restrict__ bna1, const float* __restrict__ bnc1) {
    __shared__ float sPart[4][128];
    int q = blockIdx.x;
    int tid = threadIdx.x, wid = tid >> 5, lane = tid & 31;
    int s = d_rowstart[q], t = d_rowstart[q + 1];
    float4 acc = make_float4(0.f, 0.f, 0.f, 0.f);
    for (int i = s + wid; i < t; i += 4) {
        int r = d_rsorted[i];
        float w = d_wsorted[i];
        float4 y = *(const float4*)(d_Y1 + (size_t)r * C0 + lane * 4);
        acc.x = fmaf(w, y.x, acc.x); acc.y = fmaf(w, y.y, acc.y);
        acc.z = fmaf(w, y.z, acc.z); acc.w = fmaf(w, y.w, acc.w);
    }
    sPart[wid][lane * 4 + 0] = acc.x;
    sPart[wid][lane * 4 + 1] = acc.y;
    sPart[wid][lane * 4 + 2] = acc.z;
    sPart[wid][lane * 4 + 3] = acc.w;
    __syncthreads();
    int c = tid;  // 128 threads
    float sum = sPart[0][c] + sPart[1][c] + sPart[2][c] + sPart[3][c];
    float qf = 0.f;
    if (t > s) qf = bna0[c] * sum * (1.0f / d_wsum[q]) + bnc0[c];
    float sv = d_S[(size_t)q * C0 + c];
    float v = fmaxf(qf + bna1[c] * sv + bnc1[c], 0.f);
    uint16_t h, l;
    split2(v, h, l);
    ((uint16_t*)d_X0H)[(size_t)q * C0 + c] = h;
    ((uint16_t*)d_X0L)[(size_t)q * C0 + c] = l;
}

// ---------------- x1 = relu(a*Y + c), emit split bf16 (C=256) ----------------
__global__ void k_bnrelu_split(const float* __restrict__ Y, int n4,
                               const float* __restrict__ bna, const float* __restrict__ bnc) {
    int qd = blockIdx.x * blockDim.x + threadIdx.x;
    if (qd >= n4) return;
    int i = qd * 4;
    int c = i & 255;
    float4 y = *(float4*)(Y + i);
    float v0 = fmaxf(bna[c] * y.x + bnc[c], 0.f);
    float v1 = fmaxf(bna[c + 1] * y.y + bnc[c + 1], 0.f);
    float v2 = fmaxf(bna[c + 2] * y.z + bnc[c + 2], 0.f);
    float v3 = fmaxf(bna[c + 3] * y.w + bnc[c + 3], 0.f);
    uint16_t h[4], l[4];
    split2(v0, h[0], l[0]); split2(v1, h[1], l[1]);
    split2(v2, h[2], l[2]); split2(v3, h[3], l[3]);
    *(uint2*)((uint16_t*)d_X1H + i) = make_uint2(h[0] | ((uint32_t)h[1] << 16), h[2] | ((uint32_t)h[3] << 16));
    *(uint2*)((uint16_t*)d_X1L + i) = make_uint2(l[0] | ((uint32_t)l[1] << 16), l[2] | ((uint32_t)l[3] << 16));
}

// ---------------- out = relu(a*Y + c) fp32 (C=256) ----------------
__global__ void k_bnrelu_out(const float* __restrict__ Y, float* __restrict__ X, int n4,
                             const float* __restrict__ bna, const float* __restrict__ bnc) {
    int qd = blockIdx.x * blockDim.x + threadIdx.x;
    if (qd >= n4) return;
    int i = qd * 4;
    int c = i & 255;
    float4 y = *(float4*)(Y + i);
    float4 o;
    o.x = fmaxf(bna[c] * y.x + bnc[c], 0.f);
    o.y = fmaxf(bna[c + 1] * y.y + bnc[c + 1], 0.f);
    o.z = fmaxf(bna[c + 2] * y.z + bnc[c + 2], 0.f);
    o.w = fmaxf(bna[c + 3] * y.w + bnc[c + 3], 0.f);
    *(float4*)(X + i) = o;
}

// ---------------- launcher ----------------
extern "C" void kernel_launch(void* const* d_in, const int* in_sizes, int n_in,
                              void* d_out, int out_size) {
    const float* ref_bxyz   = (const float*)d_in[0];
    const float* ref_feat   = (const float*)d_in[1];
    const float* query_bxyz = (const float*)d_in[2];
    const float* query_feat = (const float*)d_in[3];
    const int*   e_ref      = (const int*)d_in[4];
    const int*   e_query    = (const int*)d_in[5];
    const float* Wf0   = (const float*)d_in[6];
    const float* gf0   = (const float*)d_in[7];
    const float* bf0   = (const float*)d_in[8];
    const float* Ws0   = (const float*)d_in[9];
    const float* gs0   = (const float*)d_in[10];
    const float* bs0   = (const float*)d_in[11];
    const float* W1    = (const float*)d_in[12];
    const float* g1    = (const float*)d_in[14];
    const float* beta1 = (const float*)d_in[15];
    const float* W2    = (const float*)d_in[16];
    const float* g2    = (const float*)d_in[18];
    const float* beta2 = (const float*)d_in[19];
    float* out = (float*)d_out;

    float *pY1, *pS, *pY2, *pY3, *pPart, *pBN;
    cudaGetSymbolAddress((void**)&pY1, d_Y1);
    cudaGetSymbolAddress((void**)&pS,  d_S);
    cudaGetSymbolAddress((void**)&pY2, d_Y2);
    cudaGetSymbolAddress((void**)&pY3, d_Y3);
    cudaGetSymbolAddress((void**)&pPart, d_partial);
    cudaGetSymbolAddress((void**)&pBN, d_bn);
    float* pPartA = pPart;
    float* pPartB = pPart + 400 * 1024;
    float* bna0 = pBN;            float* bnc0 = pBN + 256;
    float* bna1 = pBN + 512;      float* bnc1 = pBN + 768;
    float* bna2 = pBN + 1024;     float* bnc2 = pBN + 1280;
    float* bna3 = pBN + 1536;     float* bnc3 = pBN + 1792;

    __nv_bfloat16 *pRefH, *pRefL, *pQH, *pQL, *pX0H, *pX0L, *pX1H, *pX1L;
    __nv_bfloat16 *pWf0H, *pWf0L, *pWs0H, *pWs0L, *pW1H, *pW1L, *pW2H, *pW2L;
    cudaGetSymbolAddress((void**)&pRefH, d_refH); cudaGetSymbolAddress((void**)&pRefL, d_refL);
    cudaGetSymbolAddress((void**)&pQH, d_qH);     cudaGetSymbolAddress((void**)&pQL, d_qL);
    cudaGetSymbolAddress((void**)&pX0H, d_X0H);   cudaGetSymbolAddress((void**)&pX0L, d_X0L);
    cudaGetSymbolAddress((void**)&pX1H, d_X1H);   cudaGetSymbolAddress((void**)&pX1L, d_X1L);
    cudaGetSymbolAddress((void**)&pWf0H, d_Wf0H); cudaGetSymbolAddress((void**)&pWf0L, d_Wf0L);
    cudaGetSymbolAddress((void**)&pWs0H, d_Ws0H); cudaGetSymbolAddress((void**)&pWs0L, d_Ws0L);
    cudaGetSymbolAddress((void**)&pW1H, d_W1H);   cudaGetSymbolAddress((void**)&pW1L, d_W1L);
    cudaGetSymbolAddress((void**)&pW2H, d_W2H);   cudaGetSymbolAddress((void**)&pW2L, d_W2L);

    static cudaStream_t s1 = nullptr, s2 = nullptr;
    static cudaEvent_t evStart, evEdge, evS;
    if (!s1) {
        cudaStreamCreateWithFlags(&s1, cudaStreamNonBlocking);
        cudaStreamCreateWithFlags(&s2, cudaStreamNonBlocking);
        cudaEventCreateWithFlags(&evStart, cudaEventDisableTiming);
        cudaEventCreateWithFlags(&evEdge, cudaEventDisableTiming);
        cudaEventCreateWithFlags(&evS, cudaEventDisableTiming);
    }

    cudaEventRecord(evStart, 0);

    // s1: edge preprocessing (fully independent)
    cudaStreamWaitEvent(s1, evStart, 0);
    k_init<<<(N_QP / 4 + 256) / 256, 256, 0, s1>>>();
    k_edge<<<(NEDGE + 255) / 256, 256, 0, s1>>>((const float4*)ref_bxyz,
                                                (const float4*)query_bxyz, e_ref, e_query);
    k_scan<<<1, 1024, 0, s1>>>();
    k_fill<<<(NEDGE + 255) / 256, 256, 0, s1>>>(e_query, e_ref);
    cudaEventRecord(evEdge, s1);

    // s2: other splits + skip-branch GEMM + its BN finalize
    cudaStreamWaitEvent(s2, evStart, 0);
    k_split_b<<<(QB_TOT + 255) / 256, 256, 0, s2>>>(query_feat, Ws0, W1, W2);
    {
        dim3 g((N_QP + 127) / 128, 1);
        k_mma<<<g, 256, 0, s2>>>(pQH, pQL, pWs0H, pWs0L, pS, pPartB, N_QP, C0, C0);
        k_bnfinal<<<1, 1024, 0, s2>>>(C0, N_QP, g.x, pPartB, gs0, bs0, bna1, bnc1);
    }
    cudaEventRecord(evS, s2);

    // main chain
    k_split_a<<<(QA_TOT + 255) / 256, 256>>>(ref_feat, Wf0);
    {
        dim3 g((N_REFP + 127) / 128, 1);
        k_mma<<<g, 256>>>(pRefH, pRefL, pWf0H, pWf0L, pY1, pPartA, N_REFP, C0, C0);
        k_bnfinal<<<1, 1024>>>(C0, N_REFP, g.x, pPartA, gf0, bf0, bna0, bnc0);
    }
    cudaStreamWaitEvent(0, evEdge, 0);
    cudaStreamWaitEvent(0, evS, 0);
    k_gather_x0<<<N_QP, 128>>>(bna0, bnc0, bna1, bnc1);

    {
        dim3 g((N_QP + 127) / 128, 2);
        k_mma<<<g, 256>>>(pX0H, pX0L, pW1H, pW1L, pY2, pPartA, N_QP, C1, C0);
        k_bnfinal<<<1, 1024>>>(C1, N_QP, g.x, pPartA, g1, beta1, bna2, bnc2);
    }
    k_bnrelu_split<<<(N_QP * C1 / 4 + 255) / 256, 256>>>(pY2, N_QP * C1 / 4, bna2, bnc2);

    {
        dim3 g((N_QP + 127) / 128, 2);
        k_mma<<<g, 256>>>(pX1H, pX1L, pW2H, pW2L, pY3, pPartA, N_QP, C1, C1);
        k_bnfinal<<<1, 1024>>>(C1, N_QP, g.x, pPartA, g2, beta2, bna3, bnc3);
    }
    k_bnrelu_out<<<(N_QP * C1 / 4 + 255) / 256, 256>>>(pY3, out, N_QP * C1 / 4, bna3, bnc3);
}

// round 12
// speedup vs baseline: 2.8944x; 1.0770x over previous
#include <cuda_runtime.h>
#include <cuda_bf16.h>
#include <math.h>
#include <cstdint>

#define N_QP   25000
#define N_REFP 50000
#define NEDGE  400000
#define C0     128
#define C1     256
#define BN_EPS 1e-5f

// ---------------- scratch ----------------
__device__ float d_w[NEDGE];
__device__ float d_wsum[N_QP];
__device__ int   d_deg[N_QP];
__device__ int   d_cursor[N_QP];
__device__ int   d_rowstart[N_QP + 1];
__device__ int   d_rsorted[NEDGE];
__device__ float d_wsorted[NEDGE];
__device__ float d_Y1[(size_t)N_REFP * C0];
__device__ float d_S [(size_t)N_QP * C0];
__device__ float d_Y2[(size_t)N_QP * C1];
__device__ float d_Y3[(size_t)N_QP * C1];
__device__ float d_partial[600 * 1024];      // region A @0, region B @400*1024
__device__ float d_bn[4][2][256];
__device__ __nv_bfloat16 d_refH[(size_t)N_REFP * C0], d_refL[(size_t)N_REFP * C0];
__device__ __nv_bfloat16 d_qH[(size_t)N_QP * C0],     d_qL[(size_t)N_QP * C0];
__device__ __nv_bfloat16 d_X0H[(size_t)N_QP * C0],    d_X0L[(size_t)N_QP * C0];
__device__ __nv_bfloat16 d_X1H[(size_t)N_QP * C1],    d_X1L[(size_t)N_QP * C1];
__device__ __nv_bfloat16 d_Wf0H[C0 * C0], d_Wf0L[C0 * C0];
__device__ __nv_bfloat16 d_Ws0H[C0 * C0], d_Ws0L[C0 * C0];
__device__ __nv_bfloat16 d_W1H[C0 * C1],  d_W1L[C0 * C1];
__device__ __nv_bfloat16 d_W2H[C1 * C1],  d_W2L[C1 * C1];

// ======================= helpers =======================
__device__ __forceinline__ uint32_t smem_u32(const void* p) {
    uint32_t a;
    asm("{ .reg .u64 t; cvta.to.shared.u64 t, %1; cvt.u32.u64 %0, t; }" : "=r"(a) : "l"(p));
    return a;
}
__device__ __forceinline__ void ldsm_x4(uint32_t& r0, uint32_t& r1, uint32_t& r2, uint32_t& r3,
                                        uint32_t addr) {
    asm volatile("ldmatrix.sync.aligned.m8n8.x4.shared.b16 {%0,%1,%2,%3}, [%4];"
                 : "=r"(r0), "=r"(r1), "=r"(r2), "=r"(r3) : "r"(addr));
}
__device__ __forceinline__ void ldsm_x4_t(uint32_t& r0, uint32_t& r1, uint32_t& r2, uint32_t& r3,
                                          uint32_t addr) {
    asm volatile("ldmatrix.sync.aligned.m8n8.x4.trans.shared.b16 {%0,%1,%2,%3}, [%4];"
                 : "=r"(r0), "=r"(r1), "=r"(r2), "=r"(r3) : "r"(addr));
}
__device__ __forceinline__ void mma_bf16(float* c, const uint32_t* a, const uint32_t* b) {
    asm volatile(
        "mma.sync.aligned.m16n8k16.row.col.f32.bf16.bf16.f32 "
        "{%0,%1,%2,%3}, {%4,%5,%6,%7}, {%8,%9}, {%0,%1,%2,%3};"
        : "+f"(c[0]), "+f"(c[1]), "+f"(c[2]), "+f"(c[3])
        : "r"(a[0]), "r"(a[1]), "r"(a[2]), "r"(a[3]), "r"(b[0]), "r"(b[1]));
}
__device__ __forceinline__ void cpa16(uint32_t dst, const void* src, int valid) {
    asm volatile("cp.async.cg.shared.global [%0], [%1], 16, %2;"
                 :: "r"(dst), "l"(src), "r"(valid ? 16 : 0) : "memory");
}
__device__ __forceinline__ void split2(float v, uint16_t& h, uint16_t& l) {
    __nv_bfloat16 bh = __float2bfloat16(v);
    __nv_bfloat16 bl = __float2bfloat16(v - __bfloat162float(bh));
    h = *(uint16_t*)&bh; l = *(uint16_t*)&bl;
}
__device__ __forceinline__ void split4_store(const float* X, uint16_t* H, uint16_t* L, int q) {
    float4 v = *(const float4*)(X + q * 4);
    uint16_t h[4], l[4];
    split2(v.x, h[0], l[0]); split2(v.y, h[1], l[1]);
    split2(v.z, h[2], l[2]); split2(v.w, h[3], l[3]);
    *(uint2*)(H + q * 4) = make_uint2(h[0] | ((uint32_t)h[1] << 16), h[2] | ((uint32_t)h[3] << 16));
    *(uint2*)(L + q * 4) = make_uint2(l[0] | ((uint32_t)l[1] << 16), l[2] | ((uint32_t)l[3] << 16));
}

// ---------------- split kernels ----------------
#define QR  1600000
#define QQ  800000
#define QW0 4096
#define QW1 4096
#define QW2 8192
#define QW3 16384
#define QA_TOT (QR + QW0)
#define QB_TOT (QQ + QW1 + QW2 + QW3)
__global__ void k_split_a(const float* __restrict__ ref, const float* __restrict__ Wf0) {
    int i = blockIdx.x * blockDim.x + threadIdx.x;
    if (i >= QA_TOT) return;
    if (i < QR) { split4_store(ref, (uint16_t*)d_refH, (uint16_t*)d_refL, i); return; }
    i -= QR;
    split4_store(Wf0, (uint16_t*)d_Wf0H, (uint16_t*)d_Wf0L, i);
}
__global__ void k_split_b(const float* __restrict__ qf, const float* __restrict__ Ws0,
                          const float* __restrict__ W1, const float* __restrict__ W2) {
    int i = blockIdx.x * blockDim.x + threadIdx.x;
    if (i >= QB_TOT) return;
    if (i < QQ) { split4_store(qf, (uint16_t*)d_qH, (uint16_t*)d_qL, i); return; }
    i -= QQ;
    if (i < QW1) { split4_store(Ws0, (uint16_t*)d_Ws0H, (uint16_t*)d_Ws0L, i); return; }
    i -= QW1;
    if (i < QW2) { split4_store(W1, (uint16_t*)d_W1H, (uint16_t*)d_W1L, i); return; }
    i -= QW2;
    split4_store(W2, (uint16_t*)d_W2H, (uint16_t*)d_W2L, i);
}

// ---------------- init ----------------
__global__ void k_init() {
    int i = blockIdx.x * blockDim.x + threadIdx.x;
    if (i >= N_QP / 4 + 1) return;
    if (i * 4 + 3 < N_QP) {
        *(float4*)(d_wsum + i * 4) = make_float4(0.f, 0.f, 0.f, 0.f);
        *(int4*)(d_deg + i * 4) = make_int4(0, 0, 0, 0);
        *(int4*)(d_cursor + i * 4) = make_int4(0, 0, 0, 0);
    } else {
        for (int j = i * 4; j < N_QP; j++) { d_wsum[j] = 0.f; d_deg[j] = 0; d_cursor[j] = 0; }
    }
}

// ---------------- pipelined split-bf16 GEMM, term-reordered tile reuse ----------------
// Terms per K-chunk: (Ah,Bh), (Ah,Bl), (Al,Bh) — 4 tile loads/chunk instead of 6.
// Slots: Ah->A0 always, Al->A1 always; Bh_k->B[k&1], Bl_k->B[(k&1)^1].
#define KC 32
#define A_STRIDE 40
#define B_STRIDE 136
__global__ __launch_bounds__(256, 2)
void k_mma(const __nv_bfloat16* __restrict__ Ah, const __nv_bfloat16* __restrict__ Al,
           const __nv_bfloat16* __restrict__ Bh, const __nv_bfloat16* __restrict__ Bl,
           float* __restrict__ C, float* __restrict__ partial, int M, int N, int K) {
    __shared__ __align__(16) uint16_t sA[2][128 * A_STRIDE];
    __shared__ __align__(16) uint16_t sB[2][KC * B_STRIDE];
    __shared__ float sS[8][32], sS2[8][32];
    int tid = threadIdx.x, wid = tid >> 5, lane = tid & 31;
    int bm = blockIdx.x * 128, bn = blockIdx.y * 128;
    int wm = (wid & 1) * 64, wn = (wid >> 1) * 32;
    int mat = lane >> 3, r = lane & 7;
    int kpt = K >> 5;
    int nst = 3 * kpt;

    float acc[4][4][4];
    #pragma unroll
    for (int i = 0; i < 4; i++)
        #pragma unroll
        for (int j = 0; j < 4; j++)
            #pragma unroll
            for (int v = 0; v < 4; v++) acc[i][j][v] = 0.f;

    uint32_t aBase[2] = { smem_u32(sA[0]), smem_u32(sA[1]) };
    uint32_t bBase[2] = { smem_u32(sB[0]), smem_u32(sB[1]) };

    auto issueA = [&](const __nv_bfloat16* Ap, int koff, int slot) {
        #pragma unroll
        for (int i = 0; i < 2; i++) {
            int seg = i * 256 + tid;
            int row = seg >> 2, cs = (seg & 3) << 3;
            cpa16(aBase[slot] + (row * A_STRIDE + cs) * 2,
                  Ap + (size_t)(bm + row) * K + koff + cs, (bm + row) < M);
        }
    };
    auto issueB = [&](const __nv_bfloat16* Bp, int koff, int slot) {
        #pragma unroll
        for (int i = 0; i < 2; i++) {
            int seg = i * 256 + tid;
            int row = seg >> 4, cs = (seg & 15) << 3;
            cpa16(bBase[slot] + (row * B_STRIDE + cs) * 2,
                  Bp + (size_t)(koff + row) * N + bn + cs, 1);
        }
    };

    // prologue: stage 0 tiles (Ah_0 -> A0, Bh_0 -> B0)
    issueA(Ah, 0, 0);
    issueB(Bh, 0, 0);
    asm volatile("cp.async.commit_group;" ::: "memory");

    for (int s = 0; s < nst; s++) {
        int k = s / 3, t = s - 3 * k;
        if (s + 1 < nst) {
            int s1 = s + 1, k1 = s1 / 3, t1 = s1 - 3 * k1;
            if (t1 == 0) {                       // next chunk: Ah, Bh
                issueA(Ah, k1 << 5, 0);
                issueB(Bh, k1 << 5, k1 & 1);
            } else if (t1 == 1) {                // same chunk: Bl only
                issueB(Bl, k1 << 5, (k1 & 1) ^ 1);
            } else {                             // same chunk: Al only
                issueA(Al, k1 << 5, 1);
            }
            asm volatile("cp.async.commit_group;" ::: "memory");
            asm volatile("cp.async.wait_group 1;" ::: "memory");
        } else {
            asm volatile("cp.async.wait_group 0;" ::: "memory");
        }
        __syncthreads();
        int as = (t == 2) ? 1 : 0;
        int bs = (t == 1) ? ((k & 1) ^ 1) : (k & 1);
        #pragma unroll
        for (int ks = 0; ks < KC / 16; ks++) {
            uint32_t a[4][4], b[4][2];
            #pragma unroll
            for (int mt = 0; mt < 4; mt++) {
                int mrow = wm + mt * 16 + (mat & 1) * 8 + r;
                int kcol = ks * 16 + (mat >> 1) * 8;
                ldsm_x4(a[mt][0], a[mt][1], a[mt][2], a[mt][3],
                        aBase[as] + (mrow * A_STRIDE + kcol) * 2);
            }
            #pragma unroll
            for (int nt = 0; nt < 2; nt++) {
                int krow = ks * 16 + (mat & 1) * 8 + r;
                int ncol = wn + nt * 16 + (mat >> 1) * 8;
                ldsm_x4_t(b[nt * 2][0], b[nt * 2][1], b[nt * 2 + 1][0], b[nt * 2 + 1][1],
                          bBase[bs] + (krow * B_STRIDE + ncol) * 2);
            }
            #pragma unroll
            for (int mt = 0; mt < 4; mt++)
                #pragma unroll
                for (int nt = 0; nt < 4; nt++)
                    mma_bf16(acc[mt][nt], a[mt], b[nt]);
        }
        __syncthreads();
    }

    int g = lane >> 2, tg = lane & 3;
    #pragma unroll
    for (int mt = 0; mt < 4; mt++) {
        #pragma unroll
        for (int nt = 0; nt < 4; nt++) {
            int row0 = bm + wm + mt * 16 + g;
            int col = bn + wn + nt * 8 + tg * 2;
            if (row0 < M) {
                C[(size_t)row0 * N + col] = acc[mt][nt][0];
                C[(size_t)row0 * N + col + 1] = acc[mt][nt][1];
            }
            int row1 = row0 + 8;
            if (row1 < M) {
                C[(size_t)row1 * N + col] = acc[mt][nt][2];
                C[(size_t)row1 * N + col + 1] = acc[mt][nt][3];
            }
        }
    }

    // fused column stats (rows >= M contributed exact zeros)
    #pragma unroll
    for (int nt = 0; nt < 4; nt++) {
        #pragma unroll
        for (int p = 0; p < 2; p++) {
            float ss = 0.f, qq = 0.f;
            #pragma unroll
            for (int mt = 0; mt < 4; mt++) {
                float a0 = acc[mt][nt][p], a1 = acc[mt][nt][p + 2];
                ss += a0 + a1;
                qq += a0 * a0 + a1 * a1;
            }
            #pragma unroll
            for (int off = 16; off >= 4; off >>= 1) {
                ss += __shfl_down_sync(0xffffffff, ss, off);
                qq += __shfl_down_sync(0xffffffff, qq, off);
            }
            if (g == 0) {
                sS[wid][nt * 8 + tg * 2 + p] = ss;
                sS2[wid][nt * 8 + tg * 2 + p] = qq;
            }
        }
    }
    __syncthreads();
    if (tid < 128) {
        int w0 = (tid >> 5) * 2, lc = tid & 31;
        partial[blockIdx.x * 1024 + bn + tid] = sS[w0][lc] + sS[w0 + 1][lc];
        partial[blockIdx.x * 1024 + 512 + bn + tid] = sS2[w0][lc] + sS2[w0 + 1][lc];
    }
}

// ---------------- edge weights + degree histogram ----------------
__global__ void k_edge(const float4* __restrict__ ref_bxyz,
                       const float4* __restrict__ query_bxyz,
                       const int* __restrict__ e_ref,
                       const int* __restrict__ e_query) {
    int e = blockIdx.x * blockDim.x + threadIdx.x;
    if (e >= NEDGE) return;
    int r = e_ref[e], q = e_query[e];
    float4 rb = ref_bxyz[r];
    float4 qb = query_bxyz[q];
    float dx = rb.y - qb.y, dy = rb.z - qb.z, dz = rb.w - qb.w;
    float dist = sqrtf(dx * dx + dy * dy + dz * dz);
    float w = 1.0f / (dist + 1e-8f);
    d_w[e] = w;
    atomicAdd(&d_wsum[q], w);
    atomicAdd(&d_deg[q], 1);
}

// ---------------- single-pass scan ----------------
__global__ void k_scan() {
    __shared__ int wsum[32];
    const int CH = 25;
    int tid = threadIdx.x, lane = tid & 31, wid = tid >> 5;
    int base = tid * CH;
    int s = 0;
    #pragma unroll
    for (int i = 0; i < CH; i++) {
        int idx = base + i;
        if (idx < N_QP) s += d_deg[idx];
    }
    int v = s;
    #pragma unroll
    for (int off = 1; off < 32; off <<= 1) {
        int t = __shfl_up_sync(0xffffffff, v, off);
        if (lane >= off) v += t;
    }
    if (lane == 31) wsum[wid] = v;
    __syncthreads();
    if (wid == 0) {
        int w = wsum[lane];
        #pragma unroll
        for (int off = 1; off < 32; off <<= 1) {
            int t = __shfl_up_sync(0xffffffff, w, off);
            if (lane >= off) w += t;
        }
        wsum[lane] = w;
    }
    __syncthreads();
    int warp_excl = (wid == 0) ? 0 : wsum[wid - 1];
    int run = warp_excl + v - s;
    #pragma unroll
    for (int i = 0; i < CH; i++) {
        int idx = base + i;
        if (idx < N_QP) { d_rowstart[idx] = run; run += d_deg[idx]; }
    }
    if (base < N_QP && base + CH >= N_QP) d_rowstart[N_QP] = run;
}

// ---------------- bucket-fill: (ref_idx, weight) per slot ----------------
__global__ void k_fill(const int* __restrict__ e_query, const int* __restrict__ e_ref) {
    int e = blockIdx.x * blockDim.x + threadIdx.x;
    if (e >= NEDGE) return;
    int q = e_query[e];
    int pos = atomicAdd(&d_cursor[q], 1) + d_rowstart[q];
    d_rsorted[pos] = e_ref[e];
    d_wsorted[pos] = d_w[e];
}

// ---------------- BN finalize (parallel, 1024 threads) ----------------
__global__ void k_bnfinal(int C, int M, int NBLK, const float* __restrict__ partial,
                          const float* __restrict__ g, const float* __restrict__ b,
                          float* __restrict__ bna, float* __restrict__ bnc) {
    __shared__ float redS[4][256], redQ[4][256];
    int t = threadIdx.x;
    int c = t & 255, chunk = t >> 8;
    float s = 0.f, s2 = 0.f;
    for (int bx = chunk; bx < NBLK; bx += 4) {
        s += partial[bx * 1024 + c];
        s2 += partial[bx * 1024 + 512 + c];
    }
    redS[chunk][c] = s;
    redQ[chunk][c] = s2;
    __syncthreads();
    if (t < C) {
        float S = redS[0][t] + redS[1][t] + redS[2][t] + redS[3][t];
        float Q = redQ[0][t] + redQ[1][t] + redQ[2][t] + redQ[3][t];
        float m = S / (float)M;
        float v = Q / (float)M - m * m;
        float a = g[t] * rsqrtf(v + BN_EPS);
        bna[t] = a;
        bnc[t] = b[t] - a * m;
    }
}

// ---------------- fused gather + x0 ----------------
__global__ void k_gather_x0(const float* __restrict__ bna0, const float* __restrict__ bnc0,
                            const float* __restrict__ bna1, const float* __restrict__ bnc1) {
    __shared__ float sPart[4][128];
    int q = blockIdx.x;
    int tid = threadIdx.x, wid = tid >> 5, lane = tid & 31;
    int s = d_rowstart[q], t = d_rowstart[q + 1];
    float4 acc = make_float4(0.f, 0.f, 0.f, 0.f);
    for (int i = s + wid; i < t; i += 4) {
        int r = d_rsorted[i];
        float w = d_wsorted[i];
        float4 y = *(const float4*)(d_Y1 + (size_t)r * C0 + lane * 4);
        acc.x = fmaf(w, y.x, acc.x); acc.y = fmaf(w, y.y, acc.y);
        acc.z = fmaf(w, y.z, acc.z); acc.w = fmaf(w, y.w, acc.w);
    }
    sPart[wid][lane * 4 + 0] = acc.x;
    sPart[wid][lane * 4 + 1] = acc.y;
    sPart[wid][lane * 4 + 2] = acc.z;
    sPart[wid][lane * 4 + 3] = acc.w;
    __syncthreads();
    int c = tid;
    float sum = sPart[0][c] + sPart[1][c] + sPart[2][c] + sPart[3][c];
    float qf = 0.f;
    if (t > s) qf = bna0[c] * sum * (1.0f / d_wsum[q]) + bnc0[c];
    float sv = d_S[(size_t)q * C0 + c];
    float v = fmaxf(qf + bna1[c] * sv + bnc1[c], 0.f);
    uint16_t h, l;
    split2(v, h, l);
    ((uint16_t*)d_X0H)[(size_t)q * C0 + c] = h;
    ((uint16_t*)d_X0L)[(size_t)q * C0 + c] = l;
}

// ---------------- x1 = relu(a*Y + c), emit split bf16 (C=256) ----------------
__global__ void k_bnrelu_split(const float* __restrict__ Y, int n4,
                               const float* __restrict__ bna, const float* __restrict__ bnc) {
    int qd = blockIdx.x * blockDim.x + threadIdx.x;
    if (qd >= n4) return;
    int i = qd * 4;
    int c = i & 255;
    float4 y = *(float4*)(Y + i);
    float v0 = fmaxf(bna[c] * y.x + bnc[c], 0.f);
    float v1 = fmaxf(bna[c + 1] * y.y + bnc[c + 1], 0.f);
    float v2 = fmaxf(bna[c + 2] * y.z + bnc[c + 2], 0.f);
    float v3 = fmaxf(bna[c + 3] * y.w + bnc[c + 3], 0.f);
    uint16_t h[4], l[4];
    split2(v0, h[0], l[0]); split2(v1, h[1], l[1]);
    split2(v2, h[2], l[2]); split2(v3, h[3], l[3]);
    *(uint2*)((uint16_t*)d_X1H + i) = make_uint2(h[0] | ((uint32_t)h[1] << 16), h[2] | ((uint32_t)h[3] << 16));
    *(uint2*)((uint16_t*)d_X1L + i) = make_uint2(l[0] | ((uint32_t)l[1] << 16), l[2] | ((uint32_t)l[3] << 16));
}

// ---------------- out = relu(a*Y + c) fp32 (C=256) ----------------
__global__ void k_bnrelu_out(const float* __restrict__ Y, float* __restrict__ X, int n4,
                             const float* __restrict__ bna, const float* __restrict__ bnc) {
    int qd = blockIdx.x * blockDim.x + threadIdx.x;
    if (qd >= n4) return;
    int i = qd * 4;
    int c = i & 255;
    float4 y = *(float4*)(Y + i);
    float4 o;
    o.x = fmaxf(bna[c] * y.x + bnc[c], 0.f);
    o.y = fmaxf(bna[c + 1] * y.y + bnc[c + 1], 0.f);
    o.z = fmaxf(bna[c + 2] * y.z + bnc[c + 2], 0.f);
    o.w = fmaxf(bna[c + 3] * y.w + bnc[c + 3], 0.f);
    *(float4*)(X + i) = o;
}

// ---------------- launcher ----------------
extern "C" void kernel_launch(void* const* d_in, const int* in_sizes, int n_in,
                              void* d_out, int out_size) {
    const float* ref_bxyz   = (const float*)d_in[0];
    const float* ref_feat   = (const float*)d_in[1];
    const float* query_bxyz = (const float*)d_in[2];
    const float* query_feat = (const float*)d_in[3];
    const int*   e_ref      = (const int*)d_in[4];
    const int*   e_query    = (const int*)d_in[5];
    const float* Wf0   = (const float*)d_in[6];
    const float* gf0   = (const float*)d_in[7];
    const float* bf0   = (const float*)d_in[8];
    const float* Ws0   = (const float*)d_in[9];
    const float* gs0   = (const float*)d_in[10];
    const float* bs0   = (const float*)d_in[11];
    const float* W1    = (const float*)d_in[12];
    const float* g1    = (const float*)d_in[14];
    const float* beta1 = (const float*)d_in[15];
    const float* W2    = (const float*)d_in[16];
    const float* g2    = (const float*)d_in[18];
    const float* beta2 = (const float*)d_in[19];
    float* out = (float*)d_out;

    float *pY1, *pS, *pY2, *pY3, *pPart, *pBN;
    cudaGetSymbolAddress((void**)&pY1, d_Y1);
    cudaGetSymbolAddress((void**)&pS,  d_S);
    cudaGetSymbolAddress((void**)&pY2, d_Y2);
    cudaGetSymbolAddress((void**)&pY3, d_Y3);
    cudaGetSymbolAddress((void**)&pPart, d_partial);
    cudaGetSymbolAddress((void**)&pBN, d_bn);
    float* pPartA = pPart;
    float* pPartB = pPart + 400 * 1024;
    float* bna0 = pBN;            float* bnc0 = pBN + 256;
    float* bna1 = pBN + 512;      float* bnc1 = pBN + 768;
    float* bna2 = pBN + 1024;     float* bnc2 = pBN + 1280;
    float* bna3 = pBN + 1536;     float* bnc3 = pBN + 1792;

    __nv_bfloat16 *pRefH, *pRefL, *pQH, *pQL, *pX0H, *pX0L, *pX1H, *pX1L;
    __nv_bfloat16 *pWf0H, *pWf0L, *pWs0H, *pWs0L, *pW1H, *pW1L, *pW2H, *pW2L;
    cudaGetSymbolAddress((void**)&pRefH, d_refH); cudaGetSymbolAddress((void**)&pRefL, d_refL);
    cudaGetSymbolAddress((void**)&pQH, d_qH);     cudaGetSymbolAddress((void**)&pQL, d_qL);
    cudaGetSymbolAddress((void**)&pX0H, d_X0H);   cudaGetSymbolAddress((void**)&pX0L, d_X0L);
    cudaGetSymbolAddress((void**)&pX1H, d_X1H);   cudaGetSymbolAddress((void**)&pX1L, d_X1L);
    cudaGetSymbolAddress((void**)&pWf0H, d_Wf0H); cudaGetSymbolAddress((void**)&pWf0L, d_Wf0L);
    cudaGetSymbolAddress((void**)&pWs0H, d_Ws0H); cudaGetSymbolAddress((void**)&pWs0L, d_Ws0L);
    cudaGetSymbolAddress((void**)&pW1H, d_W1H);   cudaGetSymbolAddress((void**)&pW1L, d_W1L);
    cudaGetSymbolAddress((void**)&pW2H, d_W2H);   cudaGetSymbolAddress((void**)&pW2L, d_W2L);

    static cudaStream_t s1 = nullptr, s2 = nullptr;
    static cudaEvent_t evStart, evEdge, evS;
    if (!s1) {
        cudaStreamCreateWithFlags(&s1, cudaStreamNonBlocking);
        cudaStreamCreateWithFlags(&s2, cudaStreamNonBlocking);
        cudaEventCreateWithFlags(&evStart, cudaEventDisableTiming);
        cudaEventCreateWithFlags(&evEdge, cudaEventDisableTiming);
        cudaEventCreateWithFlags(&evS, cudaEventDisableTiming);
    }

    cudaEventRecord(evStart, 0);

    // s1: edge preprocessing (fully independent)
    cudaStreamWaitEvent(s1, evStart, 0);
    k_init<<<(N_QP / 4 + 256) / 256, 256, 0, s1>>>();
    k_edge<<<(NEDGE + 255) / 256, 256, 0, s1>>>((const float4*)ref_bxyz,
                                                (const float4*)query_bxyz, e_ref, e_query);
    k_scan<<<1, 1024, 0, s1>>>();
    k_fill<<<(NEDGE + 255) / 256, 256, 0, s1>>>(e_query, e_ref);
    cudaEventRecord(evEdge, s1);

    // s2: other splits + skip-branch GEMM + its BN finalize
    cudaStreamWaitEvent(s2, evStart, 0);
    k_split_b<<<(QB_TOT + 255) / 256, 256, 0, s2>>>(query_feat, Ws0, W1, W2);
    {
        dim3 g((N_QP + 127) / 128, 1);
        k_mma<<<g, 256, 0, s2>>>(pQH, pQL, pWs0H, pWs0L, pS, pPartB, N_QP, C0, C0);
        k_bnfinal<<<1, 1024, 0, s2>>>(C0, N_QP, g.x, pPartB, gs0, bs0, bna1, bnc1);
    }
    cudaEventRecord(evS, s2);

    // main chain
    k_split_a<<<(QA_TOT + 255) / 256, 256>>>(ref_feat, Wf0);
    {
        dim3 g((N_REFP + 127) / 128, 1);
        k_mma<<<g, 256>>>(pRefH, pRefL, pWf0H, pWf0L, pY1, pPartA, N_REFP, C0, C0);
        k_bnfinal<<<1, 1024>>>(C0, N_REFP, g.x, pPartA, gf0, bf0, bna0, bnc0);
    }
    cudaStreamWaitEvent(0, evEdge, 0);
    cudaStreamWaitEvent(0, evS, 0);
    k_gather_x0<<<N_QP, 128>>>(bna0, bnc0, bna1, bnc1);

    {
        dim3 g((N_QP + 127) / 128, 2);
        k_mma<<<g, 256>>>(pX0H, pX0L, pW1H, pW1L, pY2, pPartA, N_QP, C1, C0);
        k_bnfinal<<<1, 1024>>>(C1, N_QP, g.x, pPartA, g1, beta1, bna2, bnc2);
    }
    k_bnrelu_split<<<(N_QP * C1 / 4 + 255) / 256, 256>>>(pY2, N_QP * C1 / 4, bna2, bnc2);

    {
        dim3 g((N_QP + 127) / 128, 2);
        k_mma<<<g, 256>>>(pX1H, pX1L, pW2H, pW2L, pY3, pPartA, N_QP, C1, C1);
        k_bnfinal<<<1, 1024>>>(C1, N_QP, g.x, pPartA, g2, beta2, bna3, bnc3);
    }
    k_bnrelu_out<<<(N_QP * C1 / 4 + 255) / 256, 256>>>(pY3, out, N_QP * C1 / 4, bna3, bnc3);
}